// round 2
// baseline (speedup 1.0000x reference)
#include <cuda_runtime.h>

// ---------------- problem constants ----------------
#define B_   2
#define H_   12
#define S_   4096
#define D_   768
#define BS_  64
#define HD_  64
#define NB_  64
#define MC_  3
#define PEN_ (-10000.0f)
#define SCALE_ 0.125f   // 1/sqrt(64)

// ---------------- scratch (device globals: allocation-free) ----------------
__device__ float g_q[B_*H_*S_*HD_];    // [B,H,S,HD]
__device__ float g_k[B_*H_*S_*HD_];
__device__ float g_v[B_*H_*S_*HD_];
__device__ float g_ctx[B_*S_*D_];      // [B,S,D] (head-interleaved, from_mask applied)

// ---------------- helpers ----------------
__device__ __forceinline__ float red16_max(float v) {
    #pragma unroll
    for (int off = 1; off < 16; off <<= 1)
        v = fmaxf(v, __shfl_xor_sync(0xffffffffu, v, off));
    return v;
}
__device__ __forceinline__ float red16_sum(float v) {
    #pragma unroll
    for (int off = 1; off < 16; off <<= 1)
        v += __shfl_xor_sync(0xffffffffu, v, off);
    return v;
}

// ==========================================================================
// Kernel 1: QKV projection.  out[b,h,s,hd] = sum_d hs[b,s,d] * W[h*64+hd, d]
// 64x64 output tile per CTA, 256 threads, 4x4 regs/thread, K-tile 16.
// grid = (M/64=128, N/64=12, 3)
// ==========================================================================
__global__ __launch_bounds__(256) void qkv_kernel(
    const float* __restrict__ hs,
    const float* __restrict__ Wq,
    const float* __restrict__ Wk,
    const float* __restrict__ Wv)
{
    __shared__ float As[64][17];
    __shared__ float Bs[64][17];
    const int tid = threadIdx.x;
    const int ty = tid >> 4, tx = tid & 15;
    const int lr = tid >> 2, lc = (tid & 3) << 2;
    const int m0 = blockIdx.x << 6, n0 = blockIdx.y << 6;
    const float* W = (blockIdx.z == 0) ? Wq : (blockIdx.z == 1 ? Wk : Wv);
    float* out = (blockIdx.z == 0) ? g_q : (blockIdx.z == 1 ? g_k : g_v);

    float acc[4][4];
    #pragma unroll
    for (int i = 0; i < 4; i++)
        #pragma unroll
        for (int j = 0; j < 4; j++) acc[i][j] = 0.0f;

    for (int k0 = 0; k0 < D_; k0 += 16) {
        float4 av = *(const float4*)&hs[(m0 + lr) * D_ + k0 + lc];
        float4 bv = *(const float4*)&W [(n0 + lr) * D_ + k0 + lc];
        As[lr][lc+0] = av.x; As[lr][lc+1] = av.y; As[lr][lc+2] = av.z; As[lr][lc+3] = av.w;
        Bs[lr][lc+0] = bv.x; Bs[lr][lc+1] = bv.y; Bs[lr][lc+2] = bv.z; Bs[lr][lc+3] = bv.w;
        __syncthreads();
        #pragma unroll
        for (int kk = 0; kk < 16; kk++) {
            float a[4], b[4];
            #pragma unroll
            for (int i = 0; i < 4; i++) a[i] = As[ty + 16*i][kk];
            #pragma unroll
            for (int j = 0; j < 4; j++) b[j] = Bs[tx + 16*j][kk];
            #pragma unroll
            for (int i = 0; i < 4; i++)
                #pragma unroll
                for (int j = 0; j < 4; j++) acc[i][j] += a[i] * b[j];
        }
        __syncthreads();
    }

    const int h = blockIdx.y;   // N-tile == one head (64)
    #pragma unroll
    for (int i = 0; i < 4; i++) {
        int m = m0 + ty + 16*i;
        int b = m >> 12;            // /4096
        int s = m & (S_ - 1);
        float* dst = &out[((b * H_ + h) * S_ + s) * HD_];
        #pragma unroll
        for (int j = 0; j < 4; j++) dst[tx + 16*j] = acc[i][j];
    }
}

// ==========================================================================
// Kernel 2: BigBird sparse attention, one CTA per (b,h,query-block l).
// Online-softmax flash loop over a list of key blocks with per-block mask type:
//   0 = to_mask[b, blk*64+k]      (also used for the two full rows 0 / NB-1)
//   1 = band_mask[b,0,l-2,q, aux*64+k]
//   2 = graph: from_blocked[b,l,q] * to_blocked[b,aux,k]
// Writes ctx in [B,S,D] layout with from_mask applied.
// ==========================================================================
__global__ __launch_bounds__(256) void attn_kernel(
    const float* __restrict__ to_mask,
    const float* __restrict__ band_mask,
    const float* __restrict__ from_mask,
    const float* __restrict__ fbm,      // from_blocked_mask [B,NB,BS]
    const float* __restrict__ tbm,      // to_blocked_mask   [B,NB,BS]
    const int*   __restrict__ ga)       // graph_attn [B,H,NB,MC]
{
    extern __shared__ float smem[];
    float* Qs = smem;                 // [64][65]
    float* Ks = smem + 64*65;         // [64][65]
    float* Vs = smem + 2*64*65;       // [64][65]
    float* Ps = smem + 3*64*65;       // [64][65]

    const int l = blockIdx.x, h = blockIdx.y, b = blockIdx.z;
    const int tid = threadIdx.x;
    const int ty = tid >> 4, tx = tid & 15;

    // ---- load Q block ----
    const int qbase = ((b * H_ + h) * S_ + l * BS_) * HD_;
    for (int t = tid; t < 64 * 16; t += 256) {
        int q = t >> 4, c = (t & 15) << 2;
        float4 v = *(const float4*)&g_q[qbase + q * 64 + c];
        Qs[q*65 + c+0] = v.x; Qs[q*65 + c+1] = v.y; Qs[q*65 + c+2] = v.z; Qs[q*65 + c+3] = v.w;
    }

    // ---- key-block schedule ----
    int kb[8], mt[8], aux[8];
    int nk;
    const bool full = (l == 0 || l == NB_ - 1);
    if (full) {
        nk = NB_;
    } else {
        int gb = ((b * H_ + h) * NB_ + l) * MC_;
        int g0 = ga[gb], g1 = ga[gb+1], g2 = ga[gb+2];
        if (l == 1) {
            kb[0]=0; kb[1]=1; kb[2]=2; kb[3]=NB_-1; kb[4]=g0; kb[5]=g1; kb[6]=g2;
            mt[0]=0; mt[1]=0; mt[2]=0; mt[3]=0; mt[4]=2; mt[5]=2; mt[6]=2;
            aux[0]=0; aux[1]=0; aux[2]=0; aux[3]=0; aux[4]=g0; aux[5]=g1; aux[6]=g2;
            nk = 7;
        } else if (l == NB_ - 2) {
            kb[0]=0; kb[1]=NB_-3; kb[2]=NB_-2; kb[3]=NB_-1; kb[4]=g0; kb[5]=g1; kb[6]=g2;
            mt[0]=0; mt[1]=0; mt[2]=0; mt[3]=0; mt[4]=2; mt[5]=2; mt[6]=2;
            aux[0]=0; aux[1]=0; aux[2]=0; aux[3]=0; aux[4]=g0; aux[5]=g1; aux[6]=g2;
            nk = 7;
        } else {
            kb[0]=0; kb[1]=l-1; kb[2]=l; kb[3]=l+1; kb[4]=g0; kb[5]=g1; kb[6]=g2; kb[7]=NB_-1;
            mt[0]=0; mt[1]=1; mt[2]=1; mt[3]=1; mt[4]=2; mt[5]=2; mt[6]=2; mt[7]=0;
            aux[0]=0; aux[1]=0; aux[2]=1; aux[3]=2; aux[4]=g0; aux[5]=g1; aux[6]=g2; aux[7]=0;
            nk = 8;
        }
    }

    float m_run[4], l_run[4], acc[4][4];
    #pragma unroll
    for (int i = 0; i < 4; i++) {
        m_run[i] = -1e30f; l_run[i] = 0.0f;
        #pragma unroll
        for (int j = 0; j < 4; j++) acc[i][j] = 0.0f;
    }

    for (int it = 0; it < nk; ++it) {
        const int blk   = full ? it : kb[it];
        const int mtype = full ? 0  : mt[it];
        const int a     = full ? 0  : aux[it];

        // ---- load K and V blocks ----
        const int kvbase = ((b * H_ + h) * S_ + blk * BS_) * HD_;
        __syncthreads();   // previous iter's P@V done before overwrite
        for (int t = tid; t < 64 * 16; t += 256) {
            int r = t >> 4, c = (t & 15) << 2;
            float4 kv = *(const float4*)&g_k[kvbase + r * 64 + c];
            float4 vv = *(const float4*)&g_v[kvbase + r * 64 + c];
            Ks[r*65 + c+0] = kv.x; Ks[r*65 + c+1] = kv.y; Ks[r*65 + c+2] = kv.z; Ks[r*65 + c+3] = kv.w;
            Vs[r*65 + c+0] = vv.x; Vs[r*65 + c+1] = vv.y; Vs[r*65 + c+2] = vv.z; Vs[r*65 + c+3] = vv.w;
        }
        __syncthreads();

        // ---- S = Q K^T ----
        float s[4][4];
        #pragma unroll
        for (int i = 0; i < 4; i++)
            #pragma unroll
            for (int j = 0; j < 4; j++) s[i][j] = 0.0f;
        #pragma unroll 8
        for (int d = 0; d < 64; d++) {
            float av[4], bv[4];
            #pragma unroll
            for (int i = 0; i < 4; i++) av[i] = Qs[(ty + 16*i)*65 + d];
            #pragma unroll
            for (int j = 0; j < 4; j++) bv[j] = Ks[(tx + 16*j)*65 + d];
            #pragma unroll
            for (int i = 0; i < 4; i++)
                #pragma unroll
                for (int j = 0; j < 4; j++) s[i][j] += av[i] * bv[j];
        }

        // ---- scale + mask penalty ----
        if (mtype == 0) {
            float tmv[4];
            #pragma unroll
            for (int j = 0; j < 4; j++) tmv[j] = to_mask[b * S_ + blk * BS_ + tx + 16*j];
            #pragma unroll
            for (int i = 0; i < 4; i++)
                #pragma unroll
                for (int j = 0; j < 4; j++)
                    s[i][j] = s[i][j] * SCALE_ + (1.0f - tmv[j]) * PEN_;
        } else if (mtype == 1) {
            #pragma unroll
            for (int i = 0; i < 4; i++) {
                int q = ty + 16*i;
                const float* bm = &band_mask[((b * (NB_-4) + (l-2)) * BS_ + q) * (3*BS_) + a * BS_];
                #pragma unroll
                for (int j = 0; j < 4; j++)
                    s[i][j] = s[i][j] * SCALE_ + (1.0f - bm[tx + 16*j]) * PEN_;
            }
        } else {
            float fbv[4], tbv[4];
            #pragma unroll
            for (int i = 0; i < 4; i++) fbv[i] = fbm[(b * NB_ + l) * BS_ + ty + 16*i];
            #pragma unroll
            for (int j = 0; j < 4; j++) tbv[j] = tbm[(b * NB_ + a) * BS_ + tx + 16*j];
            #pragma unroll
            for (int i = 0; i < 4; i++)
                #pragma unroll
                for (int j = 0; j < 4; j++)
                    s[i][j] = s[i][j] * SCALE_ + (1.0f - fbv[i] * tbv[j]) * PEN_;
        }

        // ---- online softmax update (stats replicated across the 16 tx lanes) ----
        #pragma unroll
        for (int i = 0; i < 4; i++) {
            float bmax = fmaxf(fmaxf(s[i][0], s[i][1]), fmaxf(s[i][2], s[i][3]));
            bmax = red16_max(bmax);
            float mn = fmaxf(m_run[i], bmax);
            float alpha = __expf(m_run[i] - mn);
            float rs = 0.0f;
            #pragma unroll
            for (int j = 0; j < 4; j++) {
                float p = __expf(s[i][j] - mn);
                s[i][j] = p;
                rs += p;
            }
            rs = red16_sum(rs);
            l_run[i] = l_run[i] * alpha + rs;
            m_run[i] = mn;
            #pragma unroll
            for (int j = 0; j < 4; j++) acc[i][j] *= alpha;
        }

        // ---- write P, then acc += P @ V ----
        #pragma unroll
        for (int i = 0; i < 4; i++)
            #pragma unroll
            for (int j = 0; j < 4; j++)
                Ps[(ty + 16*i)*65 + tx + 16*j] = s[i][j];
        __syncthreads();

        #pragma unroll 8
        for (int kk = 0; kk < 64; kk++) {
            float pv[4], vv[4];
            #pragma unroll
            for (int i = 0; i < 4; i++) pv[i] = Ps[(ty + 16*i)*65 + kk];
            #pragma unroll
            for (int j = 0; j < 4; j++) vv[j] = Vs[kk*65 + tx + 16*j];
            #pragma unroll
            for (int i = 0; i < 4; i++)
                #pragma unroll
                for (int j = 0; j < 4; j++) acc[i][j] += pv[i] * vv[j];
        }
    }

    // ---- normalize, apply from_mask, write ctx [B,S,D] ----
    #pragma unroll
    for (int i = 0; i < 4; i++) {
        int q = ty + 16*i;
        int srow = l * BS_ + q;
        float fm = from_mask[b * S_ + srow];
        float inv = fm / l_run[i];
        float* dst = &g_ctx[(b * S_ + srow) * D_ + h * HD_];
        #pragma unroll
        for (int j = 0; j < 4; j++) dst[tx + 16*j] = acc[i][j] * inv;
    }
}

// ==========================================================================
// Kernel 3: output projection.  out[m,n] = sum_k ctx[m,k] * Wo[n,k]
// ==========================================================================
__global__ __launch_bounds__(256) void oproj_kernel(
    const float* __restrict__ Wo,
    float* __restrict__ out)
{
    __shared__ float As[64][17];
    __shared__ float Bs[64][17];
    const int tid = threadIdx.x;
    const int ty = tid >> 4, tx = tid & 15;
    const int lr = tid >> 2, lc = (tid & 3) << 2;
    const int m0 = blockIdx.x << 6, n0 = blockIdx.y << 6;

    float acc[4][4];
    #pragma unroll
    for (int i = 0; i < 4; i++)
        #pragma unroll
        for (int j = 0; j < 4; j++) acc[i][j] = 0.0f;

    for (int k0 = 0; k0 < D_; k0 += 16) {
        float4 av = *(const float4*)&g_ctx[(m0 + lr) * D_ + k0 + lc];
        float4 bv = *(const float4*)&Wo   [(n0 + lr) * D_ + k0 + lc];
        As[lr][lc+0] = av.x; As[lr][lc+1] = av.y; As[lr][lc+2] = av.z; As[lr][lc+3] = av.w;
        Bs[lr][lc+0] = bv.x; Bs[lr][lc+1] = bv.y; Bs[lr][lc+2] = bv.z; Bs[lr][lc+3] = bv.w;
        __syncthreads();
        #pragma unroll
        for (int kk = 0; kk < 16; kk++) {
            float a[4], b[4];
            #pragma unroll
            for (int i = 0; i < 4; i++) a[i] = As[ty + 16*i][kk];
            #pragma unroll
            for (int j = 0; j < 4; j++) b[j] = Bs[tx + 16*j][kk];
            #pragma unroll
            for (int i = 0; i < 4; i++)
                #pragma unroll
                for (int j = 0; j < 4; j++) acc[i][j] += a[i] * b[j];
        }
        __syncthreads();
    }

    #pragma unroll
    for (int i = 0; i < 4; i++) {
        int m = m0 + ty + 16*i;
        float* dst = &out[m * D_ + n0];
        #pragma unroll
        for (int j = 0; j < 4; j++) dst[tx + 16*j] = acc[i][j];
    }
}

// ==========================================================================
// launch
// ==========================================================================
extern "C" void kernel_launch(void* const* d_in, const int* in_sizes, int n_in,
                              void* d_out, int out_size)
{
    const float* hs        = (const float*)d_in[0];
    const float* Wq        = (const float*)d_in[1];
    const float* Wk        = (const float*)d_in[2];
    const float* Wv        = (const float*)d_in[3];
    const float* Wo        = (const float*)d_in[4];
    const float* band_mask = (const float*)d_in[5];
    const float* from_mask = (const float*)d_in[6];
    const float* to_mask   = (const float*)d_in[7];
    const float* fbm       = (const float*)d_in[8];
    const float* tbm       = (const float*)d_in[9];
    const int*   ga        = (const int*)  d_in[10];
    float* out = (float*)d_out;

    const int attn_smem = 4 * 64 * 65 * (int)sizeof(float);   // 66560 B
    cudaFuncSetAttribute(attn_kernel, cudaFuncAttributeMaxDynamicSharedMemorySize, attn_smem);

    qkv_kernel <<<dim3(128, 12, 3), 256>>>(hs, Wq, Wk, Wv);
    attn_kernel<<<dim3(NB_, H_, B_), 256, attn_smem>>>(to_mask, band_mask, from_mask, fbm, tbm, ga);
    oproj_kernel<<<dim3(128, 12), 256>>>(Wo, out);
}

// round 8
// speedup vs baseline: 1.5802x; 1.5802x over previous
#include <cuda_runtime.h>
#include <cuda_bf16.h>
#include <cstdint>

// ---------------- problem constants ----------------
#define B_   2
#define H_   12
#define S_   4096
#define D_   768
#define BS_  64
#define HD_  64
#define NB_  64
#define MC_  3
#define PEN_ (-10000.0f)
#define SCALE_ 0.125f   // 1/sqrt(64)

// ---------------- scratch (device globals: allocation-free) ----------------
__device__ float g_q[B_*H_*S_*HD_];    // [B,H,S,HD]
__device__ float g_k[B_*H_*S_*HD_];
__device__ float g_v[B_*H_*S_*HD_];
__device__ float g_ctx[B_*S_*D_];      // [B,S,D]

// ---------------- mma.sync helper (bf16 HMMA, base-target safe) ----------------
__device__ __forceinline__ void mma16816(float* d, const uint32_t* a, const uint32_t* b) {
    asm volatile(
        "mma.sync.aligned.m16n8k16.row.col.f32.bf16.bf16.f32 "
        "{%0,%1,%2,%3}, {%4,%5,%6,%7}, {%8,%9}, {%0,%1,%2,%3};"
        : "+f"(d[0]), "+f"(d[1]), "+f"(d[2]), "+f"(d[3])
        : "r"(a[0]), "r"(a[1]), "r"(a[2]), "r"(a[3]), "r"(b[0]), "r"(b[1]));
}

// split fp32 -> (hi, lo) bf16, 8 elements packed into two uint4
__device__ __forceinline__ void split8(const float* __restrict__ src, uint4& hi, uint4& lo) {
    float4 x0 = ((const float4*)src)[0];
    float4 x1 = ((const float4*)src)[1];
    float xs[8] = {x0.x, x0.y, x0.z, x0.w, x1.x, x1.y, x1.z, x1.w};
    uint32_t hw[8], lw[8];
    #pragma unroll
    for (int i = 0; i < 8; i++) {
        __nv_bfloat16 h = __float2bfloat16(xs[i]);
        float r = xs[i] - __bfloat162float(h);
        __nv_bfloat16 l = __float2bfloat16(r);
        hw[i] = (uint32_t)*(const uint16_t*)&h;
        lw[i] = (uint32_t)*(const uint16_t*)&l;
    }
    hi.x = hw[0] | (hw[1] << 16); hi.y = hw[2] | (hw[3] << 16);
    hi.z = hw[4] | (hw[5] << 16); hi.w = hw[6] | (hw[7] << 16);
    lo.x = lw[0] | (lw[1] << 16); lo.y = lw[2] | (lw[3] << 16);
    lo.z = lw[4] | (lw[5] << 16); lo.w = lw[6] | (lw[7] << 16);
}

// ==========================================================================
// HMMA bf16x3 GEMM:  C[m,n] = sum_k A[m,k] * W[n,k]
// CTA tile 128(M) x 64(N), K-chunk 32, 256 threads = 8 warps, warp tile 32x32.
// mode 0: A = Ain (hs), W in {Wq,Wk,Wv} by blockIdx.z, scatter to g_q/g_k/g_v.
// mode 1: A = g_ctx (taken from DEVICE symbol, NOT the host arg!), W = Wo,
//         write outp.
// ==========================================================================
#define STR_ 40

__global__ __launch_bounds__(256) void gemm_mma_kernel(
    const float* __restrict__ Ain,
    const float* __restrict__ W0,
    const float* __restrict__ W1,
    const float* __restrict__ W2,
    float* __restrict__ outp,
    int mode)
{
    __shared__ __align__(16) uint16_t sAhi[128 * STR_];
    __shared__ __align__(16) uint16_t sAlo[128 * STR_];
    __shared__ __align__(16) uint16_t sBhi[64 * STR_];
    __shared__ __align__(16) uint16_t sBlo[64 * STR_];

    const int tid = threadIdx.x;
    const int wid = tid >> 5, lane = tid & 31;
    const int n0 = blockIdx.x << 6;      // 768/64 = 12 n-tiles
    const int m0 = blockIdx.y << 7;      // 8192/128 = 64 m-tiles

    // CRITICAL: device-symbol scratch must be bound on the DEVICE side.
    // (Host-side &g_ctx is the host shadow; GB300 ATS dereferences it silently.)
    const float* A = (mode == 1) ? (const float*)g_ctx : Ain;
    const float* W = W0;
    if (mode == 0) W = (blockIdx.z == 0) ? W0 : (blockIdx.z == 1 ? W1 : W2);

    const int wm = (wid & 3) << 5;       // warp M offset: 0,32,64,96
    const int wn = (wid >> 2) << 5;      // warp N offset: 0,32

    // A load map: thread -> row tid/2 (0..127), col (tid&1)*16
    const int ar = tid >> 1, ac = (tid & 1) << 4;
    // B load map: thread -> row tid/4 (0..63), col (tid&3)*8
    const int br = tid >> 2, bc = (tid & 3) << 3;

    float acc[2][4][4];
    #pragma unroll
    for (int mi = 0; mi < 2; mi++)
        #pragma unroll
        for (int nj = 0; nj < 4; nj++)
            #pragma unroll
            for (int c = 0; c < 4; c++) acc[mi][nj][c] = 0.0f;

    const int lr = lane >> 2;            // 0..7
    const int lc = (lane & 3) << 1;      // 0,2,4,6

    for (int kc = 0; kc < D_ / 32; ++kc) {
        const int k0 = kc * 32;
        __syncthreads();
        // ---- load + split + STS ----
        {
            uint4 hi, lo;
            split8(&A[(size_t)(m0 + ar) * D_ + k0 + ac], hi, lo);
            *(uint4*)&sAhi[ar * STR_ + ac] = hi;
            *(uint4*)&sAlo[ar * STR_ + ac] = lo;
            split8(&A[(size_t)(m0 + ar) * D_ + k0 + ac + 8], hi, lo);
            *(uint4*)&sAhi[ar * STR_ + ac + 8] = hi;
            *(uint4*)&sAlo[ar * STR_ + ac + 8] = lo;
            split8(&W[(size_t)(n0 + br) * D_ + k0 + bc], hi, lo);
            *(uint4*)&sBhi[br * STR_ + bc] = hi;
            *(uint4*)&sBlo[br * STR_ + bc] = lo;
        }
        __syncthreads();

        // ---- consume: 2 k-steps of 16 ----
        #pragma unroll
        for (int ks = 0; ks < 2; ++ks) {
            const int kk = ks * 16;
            uint32_t ah[2][4], al[2][4], bh[4][2], bl[4][2];
            #pragma unroll
            for (int mi = 0; mi < 2; mi++) {
                int row = wm + mi * 16 + lr;
                int col = kk + lc;
                ah[mi][0] = *(const uint32_t*)&sAhi[row * STR_ + col];
                ah[mi][1] = *(const uint32_t*)&sAhi[(row + 8) * STR_ + col];
                ah[mi][2] = *(const uint32_t*)&sAhi[row * STR_ + col + 8];
                ah[mi][3] = *(const uint32_t*)&sAhi[(row + 8) * STR_ + col + 8];
                al[mi][0] = *(const uint32_t*)&sAlo[row * STR_ + col];
                al[mi][1] = *(const uint32_t*)&sAlo[(row + 8) * STR_ + col];
                al[mi][2] = *(const uint32_t*)&sAlo[row * STR_ + col + 8];
                al[mi][3] = *(const uint32_t*)&sAlo[(row + 8) * STR_ + col + 8];
            }
            #pragma unroll
            for (int nj = 0; nj < 4; nj++) {
                int n = wn + nj * 8 + lr;
                int col = kk + lc;
                bh[nj][0] = *(const uint32_t*)&sBhi[n * STR_ + col];
                bh[nj][1] = *(const uint32_t*)&sBhi[n * STR_ + col + 8];
                bl[nj][0] = *(const uint32_t*)&sBlo[n * STR_ + col];
                bl[nj][1] = *(const uint32_t*)&sBlo[n * STR_ + col + 8];
            }
            #pragma unroll
            for (int mi = 0; mi < 2; mi++)
                #pragma unroll
                for (int nj = 0; nj < 4; nj++) {
                    mma16816(acc[mi][nj], ah[mi], bh[nj]);
                    mma16816(acc[mi][nj], ah[mi], bl[nj]);
                    mma16816(acc[mi][nj], al[mi], bh[nj]);
                }
        }
    }

    // ---- epilogue ----
    #pragma unroll
    for (int mi = 0; mi < 2; mi++) {
        #pragma unroll
        for (int nj = 0; nj < 4; nj++) {
            int row0 = m0 + wm + mi * 16 + lr;
            int coff = wn + nj * 8 + lc;          // col within 64-wide n-tile
            if (mode == 0) {
                int h = blockIdx.x;               // n-tile == head
                float* dst0 = (blockIdx.z == 0) ? g_q : (blockIdx.z == 1 ? g_k : g_v);
                #pragma unroll
                for (int rr = 0; rr < 2; rr++) {
                    int m = row0 + rr * 8;
                    int b = m >> 12, s = m & (S_ - 1);
                    float* dst = &dst0[(((size_t)b * H_ + h) * S_ + s) * HD_ + coff];
                    *(float2*)dst = make_float2(acc[mi][nj][rr * 2], acc[mi][nj][rr * 2 + 1]);
                }
            } else {
                #pragma unroll
                for (int rr = 0; rr < 2; rr++) {
                    int m = row0 + rr * 8;
                    float* dst = &outp[(size_t)m * D_ + n0 + coff];
                    *(float2*)dst = make_float2(acc[mi][nj][rr * 2], acc[mi][nj][rr * 2 + 1]);
                }
            }
        }
    }
}

// ---------------- helpers for attention ----------------
__device__ __forceinline__ float red16_max(float v) {
    #pragma unroll
    for (int off = 1; off < 16; off <<= 1)
        v = fmaxf(v, __shfl_xor_sync(0xffffffffu, v, off));
    return v;
}
__device__ __forceinline__ float red16_sum(float v) {
    #pragma unroll
    for (int off = 1; off < 16; off <<= 1)
        v += __shfl_xor_sync(0xffffffffu, v, off);
    return v;
}

// ==========================================================================
// BigBird sparse attention (R2 passing version)
// ==========================================================================
__global__ __launch_bounds__(256) void attn_kernel(
    const float* __restrict__ to_mask,
    const float* __restrict__ band_mask,
    const float* __restrict__ from_mask,
    const float* __restrict__ fbm,
    const float* __restrict__ tbm,
    const int*   __restrict__ ga)
{
    extern __shared__ float smem[];
    float* Qs = smem;
    float* Ks = smem + 64*65;
    float* Vs = smem + 2*64*65;
    float* Ps = smem + 3*64*65;

    const int l = blockIdx.x, h = blockIdx.y, b = blockIdx.z;
    const int tid = threadIdx.x;
    const int ty = tid >> 4, tx = tid & 15;

    const int qbase = ((b * H_ + h) * S_ + l * BS_) * HD_;
    for (int t = tid; t < 64 * 16; t += 256) {
        int q = t >> 4, c = (t & 15) << 2;
        float4 v = *(const float4*)&g_q[qbase + q * 64 + c];
        Qs[q*65 + c+0] = v.x; Qs[q*65 + c+1] = v.y; Qs[q*65 + c+2] = v.z; Qs[q*65 + c+3] = v.w;
    }

    int kb[8], mt[8], aux[8];
    int nk;
    const bool full = (l == 0 || l == NB_ - 1);
    if (full) {
        nk = NB_;
    } else {
        int gb = ((b * H_ + h) * NB_ + l) * MC_;
        int g0 = ga[gb], g1 = ga[gb+1], g2 = ga[gb+2];
        if (l == 1) {
            kb[0]=0; kb[1]=1; kb[2]=2; kb[3]=NB_-1; kb[4]=g0; kb[5]=g1; kb[6]=g2;
            mt[0]=0; mt[1]=0; mt[2]=0; mt[3]=0; mt[4]=2; mt[5]=2; mt[6]=2;
            aux[0]=0; aux[1]=0; aux[2]=0; aux[3]=0; aux[4]=g0; aux[5]=g1; aux[6]=g2;
            nk = 7;
        } else if (l == NB_ - 2) {
            kb[0]=0; kb[1]=NB_-3; kb[2]=NB_-2; kb[3]=NB_-1; kb[4]=g0; kb[5]=g1; kb[6]=g2;
            mt[0]=0; mt[1]=0; mt[2]=0; mt[3]=0; mt[4]=2; mt[5]=2; mt[6]=2;
            aux[0]=0; aux[1]=0; aux[2]=0; aux[3]=0; aux[4]=g0; aux[5]=g1; aux[6]=g2;
            nk = 7;
        } else {
            kb[0]=0; kb[1]=l-1; kb[2]=l; kb[3]=l+1; kb[4]=g0; kb[5]=g1; kb[6]=g2; kb[7]=NB_-1;
            mt[0]=0; mt[1]=1; mt[2]=1; mt[3]=1; mt[4]=2; mt[5]=2; mt[6]=2; mt[7]=0;
            aux[0]=0; aux[1]=0; aux[2]=1; aux[3]=2; aux[4]=g0; aux[5]=g1; aux[6]=g2; aux[7]=0;
            nk = 8;
        }
    }

    float m_run[4], l_run[4], acc[4][4];
    #pragma unroll
    for (int i = 0; i < 4; i++) {
        m_run[i] = -1e30f; l_run[i] = 0.0f;
        #pragma unroll
        for (int j = 0; j < 4; j++) acc[i][j] = 0.0f;
    }

    for (int it = 0; it < nk; ++it) {
        const int blk   = full ? it : kb[it];
        const int mtype = full ? 0  : mt[it];
        const int a     = full ? 0  : aux[it];

        const int kvbase = ((b * H_ + h) * S_ + blk * BS_) * HD_;
        __syncthreads();
        for (int t = tid; t < 64 * 16; t += 256) {
            int r = t >> 4, c = (t & 15) << 2;
            float4 kv = *(const float4*)&g_k[kvbase + r * 64 + c];
            float4 vv = *(const float4*)&g_v[kvbase + r * 64 + c];
            Ks[r*65 + c+0] = kv.x; Ks[r*65 + c+1] = kv.y; Ks[r*65 + c+2] = kv.z; Ks[r*65 + c+3] = kv.w;
            Vs[r*65 + c+0] = vv.x; Vs[r*65 + c+1] = vv.y; Vs[r*65 + c+2] = vv.z; Vs[r*65 + c+3] = vv.w;
        }
        __syncthreads();

        float s[4][4];
        #pragma unroll
        for (int i = 0; i < 4; i++)
            #pragma unroll
            for (int j = 0; j < 4; j++) s[i][j] = 0.0f;
        #pragma unroll 8
        for (int d = 0; d < 64; d++) {
            float av[4], bv[4];
            #pragma unroll
            for (int i = 0; i < 4; i++) av[i] = Qs[(ty + 16*i)*65 + d];
            #pragma unroll
            for (int j = 0; j < 4; j++) bv[j] = Ks[(tx + 16*j)*65 + d];
            #pragma unroll
            for (int i = 0; i < 4; i++)
                #pragma unroll
                for (int j = 0; j < 4; j++) s[i][j] += av[i] * bv[j];
        }

        if (mtype == 0) {
            float tmv[4];
            #pragma unroll
            for (int j = 0; j < 4; j++) tmv[j] = to_mask[b * S_ + blk * BS_ + tx + 16*j];
            #pragma unroll
            for (int i = 0; i < 4; i++)
                #pragma unroll
                for (int j = 0; j < 4; j++)
                    s[i][j] = s[i][j] * SCALE_ + (1.0f - tmv[j]) * PEN_;
        } else if (mtype == 1) {
            #pragma unroll
            for (int i = 0; i < 4; i++) {
                int q = ty + 16*i;
                const float* bm = &band_mask[((b * (NB_-4) + (l-2)) * BS_ + q) * (3*BS_) + a * BS_];
                #pragma unroll
                for (int j = 0; j < 4; j++)
                    s[i][j] = s[i][j] * SCALE_ + (1.0f - bm[tx + 16*j]) * PEN_;
            }
        } else {
            float fbv[4], tbv[4];
            #pragma unroll
            for (int i = 0; i < 4; i++) fbv[i] = fbm[(b * NB_ + l) * BS_ + ty + 16*i];
            #pragma unroll
            for (int j = 0; j < 4; j++) tbv[j] = tbm[(b * NB_ + a) * BS_ + tx + 16*j];
            #pragma unroll
            for (int i = 0; i < 4; i++)
                #pragma unroll
                for (int j = 0; j < 4; j++)
                    s[i][j] = s[i][j] * SCALE_ + (1.0f - fbv[i] * tbv[j]) * PEN_;
        }

        #pragma unroll
        for (int i = 0; i < 4; i++) {
            float bmax = fmaxf(fmaxf(s[i][0], s[i][1]), fmaxf(s[i][2], s[i][3]));
            bmax = red16_max(bmax);
            float mn = fmaxf(m_run[i], bmax);
            float alpha = __expf(m_run[i] - mn);
            float rs = 0.0f;
            #pragma unroll
            for (int j = 0; j < 4; j++) {
                float p = __expf(s[i][j] - mn);
                s[i][j] = p;
                rs += p;
            }
            rs = red16_sum(rs);
            l_run[i] = l_run[i] * alpha + rs;
            m_run[i] = mn;
            #pragma unroll
            for (int j = 0; j < 4; j++) acc[i][j] *= alpha;
        }

        #pragma unroll
        for (int i = 0; i < 4; i++)
            #pragma unroll
            for (int j = 0; j < 4; j++)
                Ps[(ty + 16*i)*65 + tx + 16*j] = s[i][j];
        __syncthreads();

        #pragma unroll 8
        for (int kk = 0; kk < 64; kk++) {
            float pv[4], vv[4];
            #pragma unroll
            for (int i = 0; i < 4; i++) pv[i] = Ps[(ty + 16*i)*65 + kk];
            #pragma unroll
            for (int j = 0; j < 4; j++) vv[j] = Vs[kk*65 + tx + 16*j];
            #pragma unroll
            for (int i = 0; i < 4; i++)
                #pragma unroll
                for (int j = 0; j < 4; j++) acc[i][j] += pv[i] * vv[j];
        }
    }

    #pragma unroll
    for (int i = 0; i < 4; i++) {
        int q = ty + 16*i;
        int srow = l * BS_ + q;
        float fm = from_mask[b * S_ + srow];
        float inv = fm / l_run[i];
        float* dst = &g_ctx[(b * S_ + srow) * D_ + h * HD_];
        #pragma unroll
        for (int j = 0; j < 4; j++) dst[tx + 16*j] = acc[i][j] * inv;
    }
}

// ==========================================================================
// launch
// ==========================================================================
extern "C" void kernel_launch(void* const* d_in, const int* in_sizes, int n_in,
                              void* d_out, int out_size)
{
    const float* hs        = (const float*)d_in[0];
    const float* Wq        = (const float*)d_in[1];
    const float* Wk        = (const float*)d_in[2];
    const float* Wv        = (const float*)d_in[3];
    const float* Wo        = (const float*)d_in[4];
    const float* band_mask = (const float*)d_in[5];
    const float* from_mask = (const float*)d_in[6];
    const float* to_mask   = (const float*)d_in[7];
    const float* fbm       = (const float*)d_in[8];
    const float* tbm       = (const float*)d_in[9];
    const int*   ga        = (const int*)  d_in[10];
    float* out = (float*)d_out;

    const int attn_smem = 4 * 64 * 65 * (int)sizeof(float);   // 66560 B
    cudaFuncSetAttribute(attn_kernel, cudaFuncAttributeMaxDynamicSharedMemorySize, attn_smem);

    // QKV: M=8192 -> 64 tiles of 128, N=768 -> 12 tiles of 64 (== heads), z={q,k,v}
    gemm_mma_kernel<<<dim3(12, 64, 3), 256>>>(hs, Wq, Wk, Wv, nullptr, 0);
    attn_kernel<<<dim3(NB_, H_, B_), 256, attn_smem>>>(to_mask, band_mask, from_mask, fbm, tbm, ga);
    // mode 1 binds A = g_ctx inside the kernel (device symbol)
    gemm_mma_kernel<<<dim3(12, 64, 1), 256>>>(nullptr, Wo, nullptr, nullptr, out, 1);
}

// round 11
// speedup vs baseline: 2.8466x; 1.8014x over previous
#include <cuda_runtime.h>
#include <cuda_bf16.h>
#include <cstdint>

// ---------------- problem constants ----------------
#define B_   2
#define H_   12
#define S_   4096
#define D_   768
#define BS_  64
#define HD_  64
#define NB_  64
#define MC_  3
#define PEN_ (-10000.0f)
#define SCALE_ 0.125f   // 1/sqrt(64)

// ---------------- scratch (device globals: allocation-free) ----------------
// q/k/v stored pre-split as bf16 hi/lo (split once in projection epilogue)
__device__ uint16_t g_qh[B_*H_*S_*HD_];
__device__ uint16_t g_ql[B_*H_*S_*HD_];
__device__ uint16_t g_kh[B_*H_*S_*HD_];
__device__ uint16_t g_kl[B_*H_*S_*HD_];
__device__ uint16_t g_vh[B_*H_*S_*HD_];
__device__ uint16_t g_vl[B_*H_*S_*HD_];
__device__ float    g_ctx[B_*S_*D_];   // [B,S,D]

// ---------------- mma / ldmatrix helpers (base-target safe) ----------------
__device__ __forceinline__ void mma16816(float* d, const uint32_t* a, const uint32_t* b) {
    asm volatile(
        "mma.sync.aligned.m16n8k16.row.col.f32.bf16.bf16.f32 "
        "{%0,%1,%2,%3}, {%4,%5,%6,%7}, {%8,%9}, {%0,%1,%2,%3};"
        : "+f"(d[0]), "+f"(d[1]), "+f"(d[2]), "+f"(d[3])
        : "r"(a[0]), "r"(a[1]), "r"(a[2]), "r"(a[3]), "r"(b[0]), "r"(b[1]));
}
__device__ __forceinline__ uint32_t cvta_s(const void* p) {
    uint32_t a;
    asm("{ .reg .u64 t; cvta.to.shared.u64 t, %1; cvt.u32.u64 %0, t; }" : "=r"(a) : "l"(p));
    return a;
}
#define LDSM4(R0,R1,R2,R3,A) \
    asm volatile("ldmatrix.sync.aligned.m8n8.x4.shared.b16 {%0,%1,%2,%3}, [%4];" \
                 : "=r"(R0), "=r"(R1), "=r"(R2), "=r"(R3) : "r"(A))
#define LDSM4T(R0,R1,R2,R3,A) \
    asm volatile("ldmatrix.sync.aligned.m8n8.x4.trans.shared.b16 {%0,%1,%2,%3}, [%4];" \
                 : "=r"(R0), "=r"(R1), "=r"(R2), "=r"(R3) : "r"(A))

__device__ __forceinline__ uint32_t packbf(float a, float b) {
    __nv_bfloat162 h = __floats2bfloat162_rn(a, b);   // .x = a (low), .y = b (high)
    return *(uint32_t*)&h;
}

// split fp32 -> (hi, lo) bf16, 8 elements packed into two uint4
__device__ __forceinline__ void split8(const float* __restrict__ src, uint4& hi, uint4& lo) {
    float4 x0 = ((const float4*)src)[0];
    float4 x1 = ((const float4*)src)[1];
    float xs[8] = {x0.x, x0.y, x0.z, x0.w, x1.x, x1.y, x1.z, x1.w};
    uint32_t hw[8], lw[8];
    #pragma unroll
    for (int i = 0; i < 8; i++) {
        __nv_bfloat16 h = __float2bfloat16(xs[i]);
        float r = xs[i] - __bfloat162float(h);
        __nv_bfloat16 l = __float2bfloat16(r);
        hw[i] = (uint32_t)*(const uint16_t*)&h;
        lw[i] = (uint32_t)*(const uint16_t*)&l;
    }
    hi.x = hw[0] | (hw[1] << 16); hi.y = hw[2] | (hw[3] << 16);
    hi.z = hw[4] | (hw[5] << 16); hi.w = hw[6] | (hw[7] << 16);
    lo.x = lw[0] | (lw[1] << 16); lo.y = lw[2] | (lw[3] << 16);
    lo.z = lw[4] | (lw[5] << 16); lo.w = lw[6] | (lw[7] << 16);
}

// ==========================================================================
// HMMA bf16x3 GEMM (as R8).  mode 0: qkv proj, epilogue writes SPLIT bf16
// hi/lo to g_{q,k,v}{h,l}.  mode 1: A = g_ctx (device-side bind!), out fp32.
// ==========================================================================
#define STR_ 40

__global__ __launch_bounds__(256) void gemm_mma_kernel(
    const float* __restrict__ Ain,
    const float* __restrict__ W0,
    const float* __restrict__ W1,
    const float* __restrict__ W2,
    float* __restrict__ outp,
    int mode)
{
    __shared__ __align__(16) uint16_t sAhi[128 * STR_];
    __shared__ __align__(16) uint16_t sAlo[128 * STR_];
    __shared__ __align__(16) uint16_t sBhi[64 * STR_];
    __shared__ __align__(16) uint16_t sBlo[64 * STR_];

    const int tid = threadIdx.x;
    const int wid = tid >> 5, lane = tid & 31;
    const int n0 = blockIdx.x << 6;
    const int m0 = blockIdx.y << 7;

    const float* A = (mode == 1) ? (const float*)g_ctx : Ain;
    const float* W = W0;
    if (mode == 0) W = (blockIdx.z == 0) ? W0 : (blockIdx.z == 1 ? W1 : W2);

    const int wm = (wid & 3) << 5;
    const int wn = (wid >> 2) << 5;
    const int ar = tid >> 1, ac = (tid & 1) << 4;
    const int br = tid >> 2, bc = (tid & 3) << 3;

    float acc[2][4][4];
    #pragma unroll
    for (int mi = 0; mi < 2; mi++)
        #pragma unroll
        for (int nj = 0; nj < 4; nj++)
            #pragma unroll
            for (int c = 0; c < 4; c++) acc[mi][nj][c] = 0.0f;

    const int lr = lane >> 2;
    const int lc = (lane & 3) << 1;

    for (int kc = 0; kc < D_ / 32; ++kc) {
        const int k0 = kc * 32;
        __syncthreads();
        {
            uint4 hi, lo;
            split8(&A[(size_t)(m0 + ar) * D_ + k0 + ac], hi, lo);
            *(uint4*)&sAhi[ar * STR_ + ac] = hi;
            *(uint4*)&sAlo[ar * STR_ + ac] = lo;
            split8(&A[(size_t)(m0 + ar) * D_ + k0 + ac + 8], hi, lo);
            *(uint4*)&sAhi[ar * STR_ + ac + 8] = hi;
            *(uint4*)&sAlo[ar * STR_ + ac + 8] = lo;
            split8(&W[(size_t)(n0 + br) * D_ + k0 + bc], hi, lo);
            *(uint4*)&sBhi[br * STR_ + bc] = hi;
            *(uint4*)&sBlo[br * STR_ + bc] = lo;
        }
        __syncthreads();

        #pragma unroll
        for (int ks = 0; ks < 2; ++ks) {
            const int kk = ks * 16;
            uint32_t ah[2][4], al[2][4], bh[4][2], bl[4][2];
            #pragma unroll
            for (int mi = 0; mi < 2; mi++) {
                int row = wm + mi * 16 + lr;
                int col = kk + lc;
                ah[mi][0] = *(const uint32_t*)&sAhi[row * STR_ + col];
                ah[mi][1] = *(const uint32_t*)&sAhi[(row + 8) * STR_ + col];
                ah[mi][2] = *(const uint32_t*)&sAhi[row * STR_ + col + 8];
                ah[mi][3] = *(const uint32_t*)&sAhi[(row + 8) * STR_ + col + 8];
                al[mi][0] = *(const uint32_t*)&sAlo[row * STR_ + col];
                al[mi][1] = *(const uint32_t*)&sAlo[(row + 8) * STR_ + col];
                al[mi][2] = *(const uint32_t*)&sAlo[row * STR_ + col + 8];
                al[mi][3] = *(const uint32_t*)&sAlo[(row + 8) * STR_ + col + 8];
            }
            #pragma unroll
            for (int nj = 0; nj < 4; nj++) {
                int n = wn + nj * 8 + lr;
                int col = kk + lc;
                bh[nj][0] = *(const uint32_t*)&sBhi[n * STR_ + col];
                bh[nj][1] = *(const uint32_t*)&sBhi[n * STR_ + col + 8];
                bl[nj][0] = *(const uint32_t*)&sBlo[n * STR_ + col];
                bl[nj][1] = *(const uint32_t*)&sBlo[n * STR_ + col + 8];
            }
            #pragma unroll
            for (int mi = 0; mi < 2; mi++)
                #pragma unroll
                for (int nj = 0; nj < 4; nj++) {
                    mma16816(acc[mi][nj], ah[mi], bh[nj]);
                    mma16816(acc[mi][nj], ah[mi], bl[nj]);
                    mma16816(acc[mi][nj], al[mi], bh[nj]);
                }
        }
    }

    #pragma unroll
    for (int mi = 0; mi < 2; mi++) {
        #pragma unroll
        for (int nj = 0; nj < 4; nj++) {
            int row0 = m0 + wm + mi * 16 + lr;
            int coff = wn + nj * 8 + lc;
            if (mode == 0) {
                int h = blockIdx.x;
                uint16_t *dh, *dl;
                if (blockIdx.z == 0)      { dh = g_qh; dl = g_ql; }
                else if (blockIdx.z == 1) { dh = g_kh; dl = g_kl; }
                else                      { dh = g_vh; dl = g_vl; }
                #pragma unroll
                for (int rr = 0; rr < 2; rr++) {
                    int m = row0 + rr * 8;
                    int b = m >> 12, s = m & (S_ - 1);
                    size_t idx = (((size_t)b * H_ + h) * S_ + s) * HD_ + coff;
                    float a0 = acc[mi][nj][rr * 2], a1 = acc[mi][nj][rr * 2 + 1];
                    __nv_bfloat162 hb = __floats2bfloat162_rn(a0, a1);
                    float l0 = a0 - __bfloat162float(hb.x);
                    float l1 = a1 - __bfloat162float(hb.y);
                    __nv_bfloat162 lb = __floats2bfloat162_rn(l0, l1);
                    *(uint32_t*)&dh[idx] = *(uint32_t*)&hb;
                    *(uint32_t*)&dl[idx] = *(uint32_t*)&lb;
                }
            } else {
                #pragma unroll
                for (int rr = 0; rr < 2; rr++) {
                    int m = row0 + rr * 8;
                    float* dst = &outp[(size_t)m * D_ + n0 + coff];
                    *(float2*)dst = make_float2(acc[mi][nj][rr * 2], acc[mi][nj][rr * 2 + 1]);
                }
            }
        }
    }
}

// ==========================================================================
// HMMA BigBird attention.  128 threads = 4 warps; warp w owns query rows
// 16w..16w+15 of the 64-row block.  Q frags in regs; K/V hi/lo bf16 tiles in
// smem (stride 72, ldmatrix conflict-free); penalty tile fp32 in smem.
// Online softmax in registers (quad shuffles); P re-packed register-only.
// ==========================================================================
#define AST_ 72                       // uint16 row stride for K/V/Q tiles
#define OFF_KH 0
#define OFF_KL (64 * AST_)
#define OFF_VH (2 * 64 * AST_)
#define OFF_VL (3 * 64 * AST_)
#define OFF_PEN_BYTES (4 * 64 * AST_ * 2)          // 36864
#define PST_ 66                       // float row stride for pen tile
#define ATTN_SMEM (OFF_PEN_BYTES + 64 * PST_ * 4)  // 53760 B

extern __shared__ char asmem[];

__global__ __launch_bounds__(128) void attn_mma_kernel(
    const float* __restrict__ to_mask,
    const float* __restrict__ band_mask,
    const float* __restrict__ from_mask,
    const float* __restrict__ fbm,
    const float* __restrict__ tbm,
    const int*   __restrict__ ga)
{
    uint16_t* sT = (uint16_t*)asmem;
    float* sPen = (float*)(asmem + OFF_PEN_BYTES);
    const uint32_t sb = cvta_s(asmem);

    // heavy rows first: x=0 -> l=0, x=1 -> l=63, else l = x-1
    const int x = blockIdx.x;
    const int l = (x == 0) ? 0 : (x == 1) ? (NB_ - 1) : (x - 1);
    const int h = blockIdx.y, b = blockIdx.z;
    const int tid = threadIdx.x;
    const int wid = tid >> 5, lane = tid & 31;
    const int lr = lane >> 2, lc = (lane & 3) << 1;
    const int g8 = lane >> 3, ln8 = lane & 7;
    const int wq0 = wid << 4;

    // ---- stage Q (hi/lo) into K buffers, load Q fragments, then release ----
    {
        const size_t qbase = (((size_t)b * H_ + h) * S_ + l * BS_) * HD_;
        #pragma unroll
        for (int i = 0; i < 4; i++) {
            int idx = i * 128 + tid;
            int r = idx >> 3, c8 = (idx & 7) << 3;
            *(uint4*)&sT[OFF_KH + r * AST_ + c8] = *(const uint4*)&g_qh[qbase + r * HD_ + c8];
            *(uint4*)&sT[OFF_KL + r * AST_ + c8] = *(const uint4*)&g_ql[qbase + r * HD_ + c8];
        }
    }
    __syncthreads();

    uint32_t qh[4][4], ql[4][4];
    {
        int arow = wq0 + ln8 + ((g8 & 1) ? 8 : 0);
        int acol8 = (g8 & 2) ? 8 : 0;
        #pragma unroll
        for (int ks = 0; ks < 4; ks++) {
            uint32_t ad = sb + (uint32_t)(OFF_KH + arow * AST_ + ks * 16 + acol8) * 2;
            LDSM4(qh[ks][0], qh[ks][1], qh[ks][2], qh[ks][3], ad);
            ad = sb + (uint32_t)(OFF_KL + arow * AST_ + ks * 16 + acol8) * 2;
            LDSM4(ql[ks][0], ql[ks][1], ql[ks][2], ql[ks][3], ad);
        }
    }

    // ---- key-block schedule (same as R2) ----
    int kb[8], mt[8], aux[8];
    int nk;
    const bool full = (l == 0 || l == NB_ - 1);
    if (full) {
        nk = NB_;
    } else {
        int gb = ((b * H_ + h) * NB_ + l) * MC_;
        int g0 = ga[gb], g1 = ga[gb + 1], g2 = ga[gb + 2];
        if (l == 1) {
            kb[0]=0; kb[1]=1; kb[2]=2; kb[3]=NB_-1; kb[4]=g0; kb[5]=g1; kb[6]=g2;
            mt[0]=0; mt[1]=0; mt[2]=0; mt[3]=0; mt[4]=2; mt[5]=2; mt[6]=2;
            aux[0]=0; aux[1]=0; aux[2]=0; aux[3]=0; aux[4]=g0; aux[5]=g1; aux[6]=g2;
            nk = 7;
        } else if (l == NB_ - 2) {
            kb[0]=0; kb[1]=NB_-3; kb[2]=NB_-2; kb[3]=NB_-1; kb[4]=g0; kb[5]=g1; kb[6]=g2;
            mt[0]=0; mt[1]=0; mt[2]=0; mt[3]=0; mt[4]=2; mt[5]=2; mt[6]=2;
            aux[0]=0; aux[1]=0; aux[2]=0; aux[3]=0; aux[4]=g0; aux[5]=g1; aux[6]=g2;
            nk = 7;
        } else {
            kb[0]=0; kb[1]=l-1; kb[2]=l; kb[3]=l+1; kb[4]=g0; kb[5]=g1; kb[6]=g2; kb[7]=NB_-1;
            mt[0]=0; mt[1]=1; mt[2]=1; mt[3]=1; mt[4]=2; mt[5]=2; mt[6]=2; mt[7]=0;
            aux[0]=0; aux[1]=0; aux[2]=1; aux[3]=2; aux[4]=g0; aux[5]=g1; aux[6]=g2; aux[7]=0;
            nk = 8;
        }
    }

    float m0 = -1e30f, m1 = -1e30f, l0 = 0.0f, l1 = 0.0f;
    float acc_o[8][4];
    #pragma unroll
    for (int nj = 0; nj < 8; nj++)
        #pragma unroll
        for (int c = 0; c < 4; c++) acc_o[nj][c] = 0.0f;

    const int pr_c = tid & 63;          // pen-build column for this thread
    const int pr_h = tid >> 6;          // 0/1

    for (int it = 0; it < nk; ++it) {
        const int blk   = full ? it : kb[it];
        const int mtype = full ? 0  : mt[it];
        const int a     = full ? 0  : aux[it];

        __syncthreads();   // previous compute done before overwrite

        // ---- load K,V (bf16 hi/lo) ----
        {
            const size_t kvb = (((size_t)b * H_ + h) * S_ + blk * BS_) * HD_;
            #pragma unroll
            for (int i = 0; i < 4; i++) {
                int idx = i * 128 + tid;
                int r = idx >> 3, c8 = (idx & 7) << 3;
                *(uint4*)&sT[OFF_KH + r * AST_ + c8] = *(const uint4*)&g_kh[kvb + r * HD_ + c8];
                *(uint4*)&sT[OFF_KL + r * AST_ + c8] = *(const uint4*)&g_kl[kvb + r * HD_ + c8];
                *(uint4*)&sT[OFF_VH + r * AST_ + c8] = *(const uint4*)&g_vh[kvb + r * HD_ + c8];
                *(uint4*)&sT[OFF_VL + r * AST_ + c8] = *(const uint4*)&g_vl[kvb + r * HD_ + c8];
            }
        }
        // ---- build penalty tile ----
        if (mtype == 0) {
            float cm = to_mask[b * S_ + blk * BS_ + pr_c];
            float pv = (1.0f - cm) * PEN_;
            #pragma unroll
            for (int i = 0; i < 32; i++)
                sPen[(2 * i + pr_h) * PST_ + pr_c] = pv;
        } else if (mtype == 1) {
            const float* bmr = &band_mask[((size_t)(b * (NB_ - 4) + (l - 2)) * BS_) * (3 * BS_) + a * BS_ + pr_c];
            #pragma unroll
            for (int i = 0; i < 32; i++) {
                int r = 2 * i + pr_h;
                sPen[r * PST_ + pr_c] = (1.0f - bmr[(size_t)r * (3 * BS_)]) * PEN_;
            }
        } else {
            float cm = tbm[(b * NB_ + a) * BS_ + pr_c];
            #pragma unroll
            for (int i = 0; i < 32; i++) {
                int r = 2 * i + pr_h;
                float rm = fbm[(b * NB_ + l) * BS_ + r];
                sPen[r * PST_ + pr_c] = (1.0f - rm * cm) * PEN_;
            }
        }
        __syncthreads();

        // ---- S = Q K^T (bf16x3) ----
        float s[8][4];
        #pragma unroll
        for (int nj = 0; nj < 8; nj++)
            #pragma unroll
            for (int c = 0; c < 4; c++) s[nj][c] = 0.0f;

        {
            int brow = ln8 + ((g8 & 2) ? 8 : 0);      // + 16*njp
            int bcol8 = (g8 & 1) ? 8 : 0;
            #pragma unroll
            for (int ks = 0; ks < 4; ks++) {
                #pragma unroll
                for (int njp = 0; njp < 4; njp++) {
                    uint32_t kh[4], kl[4];
                    uint32_t ad = sb + (uint32_t)(OFF_KH + (njp * 16 + brow) * AST_ + ks * 16 + bcol8) * 2;
                    LDSM4(kh[0], kh[1], kh[2], kh[3], ad);
                    ad = sb + (uint32_t)(OFF_KL + (njp * 16 + brow) * AST_ + ks * 16 + bcol8) * 2;
                    LDSM4(kl[0], kl[1], kl[2], kl[3], ad);
                    mma16816(s[2 * njp],     qh[ks], &kh[0]);
                    mma16816(s[2 * njp],     qh[ks], &kl[0]);
                    mma16816(s[2 * njp],     ql[ks], &kh[0]);
                    mma16816(s[2 * njp + 1], qh[ks], &kh[2]);
                    mma16816(s[2 * njp + 1], qh[ks], &kl[2]);
                    mma16816(s[2 * njp + 1], ql[ks], &kh[2]);
                }
            }
        }

        // ---- scale + penalty ----
        const int r0 = wq0 + lr, r1 = r0 + 8;
        #pragma unroll
        for (int nj = 0; nj < 8; nj++) {
            float2 p0 = *(const float2*)&sPen[r0 * PST_ + nj * 8 + lc];
            float2 p1 = *(const float2*)&sPen[r1 * PST_ + nj * 8 + lc];
            s[nj][0] = s[nj][0] * SCALE_ + p0.x;
            s[nj][1] = s[nj][1] * SCALE_ + p0.y;
            s[nj][2] = s[nj][2] * SCALE_ + p1.x;
            s[nj][3] = s[nj][3] * SCALE_ + p1.y;
        }

        // ---- online softmax (rows r0, r1; stats across quad) ----
        float mx0 = -1e30f, mx1 = -1e30f;
        #pragma unroll
        for (int nj = 0; nj < 8; nj++) {
            mx0 = fmaxf(mx0, fmaxf(s[nj][0], s[nj][1]));
            mx1 = fmaxf(mx1, fmaxf(s[nj][2], s[nj][3]));
        }
        #pragma unroll
        for (int off = 1; off < 4; off <<= 1) {
            mx0 = fmaxf(mx0, __shfl_xor_sync(0xffffffffu, mx0, off));
            mx1 = fmaxf(mx1, __shfl_xor_sync(0xffffffffu, mx1, off));
        }
        float mn0 = fmaxf(m0, mx0), mn1 = fmaxf(m1, mx1);
        float al0 = __expf(m0 - mn0), al1 = __expf(m1 - mn1);
        float rs0 = 0.0f, rs1 = 0.0f;
        #pragma unroll
        for (int nj = 0; nj < 8; nj++) {
            s[nj][0] = __expf(s[nj][0] - mn0);
            s[nj][1] = __expf(s[nj][1] - mn0);
            s[nj][2] = __expf(s[nj][2] - mn1);
            s[nj][3] = __expf(s[nj][3] - mn1);
            rs0 += s[nj][0] + s[nj][1];
            rs1 += s[nj][2] + s[nj][3];
        }
        #pragma unroll
        for (int off = 1; off < 4; off <<= 1) {
            rs0 += __shfl_xor_sync(0xffffffffu, rs0, off);
            rs1 += __shfl_xor_sync(0xffffffffu, rs1, off);
        }
        l0 = l0 * al0 + rs0;  l1 = l1 * al1 + rs1;
        m0 = mn0;  m1 = mn1;
        #pragma unroll
        for (int nj = 0; nj < 8; nj++) {
            acc_o[nj][0] *= al0; acc_o[nj][1] *= al0;
            acc_o[nj][2] *= al1; acc_o[nj][3] *= al1;
        }

        // ---- acc_o += P V (P split hi/lo, register-only re-pack) ----
        {
            int vrow = ln8 + ((g8 & 1) ? 8 : 0);      // + 16*ks
            int vcol8 = (g8 & 2) ? 8 : 0;             // + 16*njp
            #pragma unroll
            for (int ks = 0; ks < 4; ks++) {
                const int t0 = 2 * ks, t1 = 2 * ks + 1;
                uint32_t aPh[4], aPl[4];
                float ph, pl;
                // a0: (row lr, keys 16ks+lc,+1)
                aPh[0] = packbf(s[t0][0], s[t0][1]);
                aPh[1] = packbf(s[t0][2], s[t0][3]);
                aPh[2] = packbf(s[t1][0], s[t1][1]);
                aPh[3] = packbf(s[t1][2], s[t1][3]);
                {
                    __nv_bfloat162 hb;
                    *(uint32_t*)&hb = aPh[0];
                    ph = s[t0][0] - __bfloat162float(hb.x); pl = s[t0][1] - __bfloat162float(hb.y);
                    aPl[0] = packbf(ph, pl);
                    *(uint32_t*)&hb = aPh[1];
                    ph = s[t0][2] - __bfloat162float(hb.x); pl = s[t0][3] - __bfloat162float(hb.y);
                    aPl[1] = packbf(ph, pl);
                    *(uint32_t*)&hb = aPh[2];
                    ph = s[t1][0] - __bfloat162float(hb.x); pl = s[t1][1] - __bfloat162float(hb.y);
                    aPl[2] = packbf(ph, pl);
                    *(uint32_t*)&hb = aPh[3];
                    ph = s[t1][2] - __bfloat162float(hb.x); pl = s[t1][3] - __bfloat162float(hb.y);
                    aPl[3] = packbf(ph, pl);
                }
                #pragma unroll
                for (int njp = 0; njp < 4; njp++) {
                    uint32_t vh[4], vl[4];
                    uint32_t ad = sb + (uint32_t)(OFF_VH + (ks * 16 + vrow) * AST_ + njp * 16 + vcol8) * 2;
                    LDSM4T(vh[0], vh[1], vh[2], vh[3], ad);
                    ad = sb + (uint32_t)(OFF_VL + (ks * 16 + vrow) * AST_ + njp * 16 + vcol8) * 2;
                    LDSM4T(vl[0], vl[1], vl[2], vl[3], ad);
                    mma16816(acc_o[2 * njp],     aPh, &vh[0]);
                    mma16816(acc_o[2 * njp],     aPh, &vl[0]);
                    mma16816(acc_o[2 * njp],     aPl, &vh[0]);
                    mma16816(acc_o[2 * njp + 1], aPh, &vh[2]);
                    mma16816(acc_o[2 * njp + 1], aPh, &vl[2]);
                    mma16816(acc_o[2 * njp + 1], aPl, &vh[2]);
                }
            }
        }
    }

    // ---- normalize, from_mask, write ctx [B,S,D] ----
    {
        const int r0 = wq0 + lr, r1 = r0 + 8;
        int srow0 = l * BS_ + r0, srow1 = l * BS_ + r1;
        float inv0 = from_mask[b * S_ + srow0] / l0;
        float inv1 = from_mask[b * S_ + srow1] / l1;
        float* d0 = &g_ctx[((size_t)b * S_ + srow0) * D_ + h * HD_];
        float* d1 = &g_ctx[((size_t)b * S_ + srow1) * D_ + h * HD_];
        #pragma unroll
        for (int nj = 0; nj < 8; nj++) {
            *(float2*)&d0[nj * 8 + lc] = make_float2(acc_o[nj][0] * inv0, acc_o[nj][1] * inv0);
            *(float2*)&d1[nj * 8 + lc] = make_float2(acc_o[nj][2] * inv1, acc_o[nj][3] * inv1);
        }
    }
}

// ==========================================================================
// launch
// ==========================================================================
extern "C" void kernel_launch(void* const* d_in, const int* in_sizes, int n_in,
                              void* d_out, int out_size)
{
    const float* hs        = (const float*)d_in[0];
    const float* Wq        = (const float*)d_in[1];
    const float* Wk        = (const float*)d_in[2];
    const float* Wv        = (const float*)d_in[3];
    const float* Wo        = (const float*)d_in[4];
    const float* band_mask = (const float*)d_in[5];
    const float* from_mask = (const float*)d_in[6];
    const float* to_mask   = (const float*)d_in[7];
    const float* fbm       = (const float*)d_in[8];
    const float* tbm       = (const float*)d_in[9];
    const int*   ga        = (const int*)  d_in[10];
    float* out = (float*)d_out;

    cudaFuncSetAttribute(attn_mma_kernel, cudaFuncAttributeMaxDynamicSharedMemorySize, ATTN_SMEM);

    gemm_mma_kernel<<<dim3(12, 64, 3), 256>>>(hs, Wq, Wk, Wv, nullptr, 0);
    attn_mma_kernel<<<dim3(NB_, H_, B_), 128, ATTN_SMEM>>>(to_mask, band_mask, from_mask, fbm, tbm, ga);
    gemm_mma_kernel<<<dim3(12, 64, 1), 256>>>(nullptr, Wo, nullptr, nullptr, out, 1);
}

// round 12
// speedup vs baseline: 2.9750x; 1.0451x over previous
#include <cuda_runtime.h>
#include <cuda_bf16.h>
#include <cstdint>

// ---------------- problem constants ----------------
#define B_   2
#define H_   12
#define S_   4096
#define D_   768
#define BS_  64
#define HD_  64
#define NB_  64
#define MC_  3
#define PEN_ (-10000.0f)
#define SCALE_ 0.125f   // 1/sqrt(64)

#define HS_N (B_*S_*D_)      // 6291456
#define W_N  (D_*D_)         // 589824

// ---------------- scratch (device globals: allocation-free) ----------------
// pre-split operands for the GEMMs
__device__ uint16_t g_ah[HS_N], g_al[HS_N];          // hidden_states hi/lo
__device__ uint16_t g_wh[4*W_N], g_wl[4*W_N];        // Wq,Wk,Wv,Wo hi/lo
__device__ uint16_t g_ch[HS_N], g_cl[HS_N];          // ctx hi/lo (attn epilogue)
// q/k/v pre-split (written by qkv projection epilogue)
__device__ uint16_t g_qh[B_*H_*S_*HD_], g_ql[B_*H_*S_*HD_];
__device__ uint16_t g_kh[B_*H_*S_*HD_], g_kl[B_*H_*S_*HD_];
__device__ uint16_t g_vh[B_*H_*S_*HD_], g_vl[B_*H_*S_*HD_];

// ---------------- helpers ----------------
__device__ __forceinline__ void mma16816(float* d, const uint32_t* a, const uint32_t* b) {
    asm volatile(
        "mma.sync.aligned.m16n8k16.row.col.f32.bf16.bf16.f32 "
        "{%0,%1,%2,%3}, {%4,%5,%6,%7}, {%8,%9}, {%0,%1,%2,%3};"
        : "+f"(d[0]), "+f"(d[1]), "+f"(d[2]), "+f"(d[3])
        : "r"(a[0]), "r"(a[1]), "r"(a[2]), "r"(a[3]), "r"(b[0]), "r"(b[1]));
}
__device__ __forceinline__ uint32_t cvta_s(const void* p) {
    uint32_t a;
    asm("{ .reg .u64 t; cvta.to.shared.u64 t, %1; cvt.u32.u64 %0, t; }" : "=r"(a) : "l"(p));
    return a;
}
#define LDSM4(R0,R1,R2,R3,A) \
    asm volatile("ldmatrix.sync.aligned.m8n8.x4.shared.b16 {%0,%1,%2,%3}, [%4];" \
                 : "=r"(R0), "=r"(R1), "=r"(R2), "=r"(R3) : "r"(A))
#define LDSM4T(R0,R1,R2,R3,A) \
    asm volatile("ldmatrix.sync.aligned.m8n8.x4.trans.shared.b16 {%0,%1,%2,%3}, [%4];" \
                 : "=r"(R0), "=r"(R1), "=r"(R2), "=r"(R3) : "r"(A))
__device__ __forceinline__ uint32_t packbf(float a, float b) {
    __nv_bfloat162 h = __floats2bfloat162_rn(a, b);
    return *(uint32_t*)&h;
}
__device__ __forceinline__ void cpasync16(uint32_t sdst, const void* gsrc) {
    asm volatile("cp.async.cg.shared.global [%0], [%1], 16;" :: "r"(sdst), "l"(gsrc));
}
#define CP_COMMIT() asm volatile("cp.async.commit_group;")

// single extern shared symbol for the TU
extern __shared__ char asmem[];

// ==========================================================================
// Kernel 0: split fp32 sources -> bf16 hi/lo (hs + 4 weight matrices)
// one float4 per thread.
// ==========================================================================
__global__ void split_inputs_kernel(
    const float* __restrict__ hs,
    const float* __restrict__ W0, const float* __restrict__ W1,
    const float* __restrict__ W2, const float* __restrict__ W3)
{
    const int nHS4 = HS_N / 4, nW4 = W_N / 4;
    int i = blockIdx.x * blockDim.x + threadIdx.x;
    if (i >= nHS4 + 4 * nW4) return;
    const float4* src;
    uint16_t *dh, *dl;
    int off;
    if (i < nHS4) {
        src = (const float4*)hs; off = i; dh = g_ah; dl = g_al;
    } else {
        int j = i - nHS4;
        int z = j / nW4; off = j - z * nW4;
        src = (const float4*)(z == 0 ? W0 : z == 1 ? W1 : z == 2 ? W2 : W3);
        dh = g_wh + (size_t)z * W_N; dl = g_wl + (size_t)z * W_N;
    }
    float4 x = src[off];
    __nv_bfloat162 h01 = __floats2bfloat162_rn(x.x, x.y);
    __nv_bfloat162 h23 = __floats2bfloat162_rn(x.z, x.w);
    __nv_bfloat162 l01 = __floats2bfloat162_rn(x.x - __bfloat162float(h01.x),
                                               x.y - __bfloat162float(h01.y));
    __nv_bfloat162 l23 = __floats2bfloat162_rn(x.z - __bfloat162float(h23.x),
                                               x.w - __bfloat162float(h23.y));
    uint2 hv, lv;
    hv.x = *(uint32_t*)&h01; hv.y = *(uint32_t*)&h23;
    lv.x = *(uint32_t*)&l01; lv.y = *(uint32_t*)&l23;
    ((uint2*)dh)[off] = hv;
    ((uint2*)dl)[off] = lv;
}

// ==========================================================================
// Kernel 1: HMMA bf16x3 GEMM on pre-split operands, cp.async double-buffered.
// CTA tile 128x64, K-chunk 32, 256 threads, warp tile 32x32.
// mode 0: A = g_ah/g_al, W = g_w{h,l}+z*W_N, epilogue -> split qkv.
// mode 1: A = g_ch/g_cl, W = g_w{h,l}+3*W_N, epilogue -> fp32 outp.
// smem: [stage][hi/lo] A(128xSTR) then B(64xSTR); 61440 B dynamic.
// ==========================================================================
#define STR_ 40
#define SA_ELT(buf,hl) (((buf)*2+(hl))*128*STR_)
#define SB_ELT(buf,hl) (4*128*STR_ + ((buf)*2+(hl))*64*STR_)
#define G2_SMEM ((4*128*STR_ + 4*64*STR_) * 2)

__global__ __launch_bounds__(256) void gemm2_kernel(float* __restrict__ outp, int mode)
{
    uint16_t* sm = (uint16_t*)asmem;
    const uint32_t sb = cvta_s(asmem);
    const int tid = threadIdx.x;
    const int wid = tid >> 5, lane = tid & 31;
    const int n0 = blockIdx.x << 6;
    const int m0 = blockIdx.y << 7;

    const uint16_t *Ah, *Al, *Wh, *Wl;
    if (mode == 0) {
        Ah = g_ah; Al = g_al;
        Wh = g_wh + (size_t)blockIdx.z * W_N;
        Wl = g_wl + (size_t)blockIdx.z * W_N;
    } else {
        Ah = g_ch; Al = g_cl;
        Wh = g_wh + (size_t)3 * W_N;
        Wl = g_wl + (size_t)3 * W_N;
    }

    const int wm = (wid & 3) << 5;
    const int wn = (wid >> 2) << 5;
    const int ar = tid >> 1, ac = (tid & 1) << 4;
    const int br = tid >> 2, bc = (tid & 3) << 3;
    const int lr = lane >> 2;
    const int lc = (lane & 3) << 1;

    float acc[2][4][4];
    #pragma unroll
    for (int mi = 0; mi < 2; mi++)
        #pragma unroll
        for (int nj = 0; nj < 4; nj++)
            #pragma unroll
            for (int c = 0; c < 4; c++) acc[mi][nj][c] = 0.0f;

    // stage loader
    auto load_stage = [&](int buf, int k0) {
        size_t ga = (size_t)(m0 + ar) * D_ + k0 + ac;
        uint32_t da0 = sb + (uint32_t)(SA_ELT(buf,0) + ar * STR_ + ac) * 2;
        uint32_t da1 = sb + (uint32_t)(SA_ELT(buf,1) + ar * STR_ + ac) * 2;
        cpasync16(da0,      Ah + ga);
        cpasync16(da0 + 16, Ah + ga + 8);
        cpasync16(da1,      Al + ga);
        cpasync16(da1 + 16, Al + ga + 8);
        size_t gb = (size_t)(n0 + br) * D_ + k0 + bc;
        uint32_t db0 = sb + (uint32_t)(SB_ELT(buf,0) + br * STR_ + bc) * 2;
        uint32_t db1 = sb + (uint32_t)(SB_ELT(buf,1) + br * STR_ + bc) * 2;
        cpasync16(db0, Wh + gb);
        cpasync16(db1, Wl + gb);
        CP_COMMIT();
    };

    load_stage(0, 0);

    const int NKC = D_ / 32;          // 24
    for (int kc = 0; kc < NKC; ++kc) {
        const int buf = kc & 1;
        if (kc + 1 < NKC) {
            load_stage(buf ^ 1, (kc + 1) * 32);
            asm volatile("cp.async.wait_group 1;" ::: "memory");
        } else {
            asm volatile("cp.async.wait_group 0;" ::: "memory");
        }
        __syncthreads();

        const uint16_t* pAh = sm + SA_ELT(buf,0);
        const uint16_t* pAl = sm + SA_ELT(buf,1);
        const uint16_t* pBh = sm + SB_ELT(buf,0);
        const uint16_t* pBl = sm + SB_ELT(buf,1);

        #pragma unroll
        for (int ks = 0; ks < 2; ++ks) {
            const int kk = ks * 16;
            uint32_t ah[2][4], al[2][4], bh[4][2], bl[4][2];
            #pragma unroll
            for (int mi = 0; mi < 2; mi++) {
                int row = wm + mi * 16 + lr;
                int col = kk + lc;
                ah[mi][0] = *(const uint32_t*)&pAh[row * STR_ + col];
                ah[mi][1] = *(const uint32_t*)&pAh[(row + 8) * STR_ + col];
                ah[mi][2] = *(const uint32_t*)&pAh[row * STR_ + col + 8];
                ah[mi][3] = *(const uint32_t*)&pAh[(row + 8) * STR_ + col + 8];
                al[mi][0] = *(const uint32_t*)&pAl[row * STR_ + col];
                al[mi][1] = *(const uint32_t*)&pAl[(row + 8) * STR_ + col];
                al[mi][2] = *(const uint32_t*)&pAl[row * STR_ + col + 8];
                al[mi][3] = *(const uint32_t*)&pAl[(row + 8) * STR_ + col + 8];
            }
            #pragma unroll
            for (int nj = 0; nj < 4; nj++) {
                int n = wn + nj * 8 + lr;
                int col = kk + lc;
                bh[nj][0] = *(const uint32_t*)&pBh[n * STR_ + col];
                bh[nj][1] = *(const uint32_t*)&pBh[n * STR_ + col + 8];
                bl[nj][0] = *(const uint32_t*)&pBl[n * STR_ + col];
                bl[nj][1] = *(const uint32_t*)&pBl[n * STR_ + col + 8];
            }
            #pragma unroll
            for (int mi = 0; mi < 2; mi++)
                #pragma unroll
                for (int nj = 0; nj < 4; nj++) {
                    mma16816(acc[mi][nj], ah[mi], bh[nj]);
                    mma16816(acc[mi][nj], ah[mi], bl[nj]);
                    mma16816(acc[mi][nj], al[mi], bh[nj]);
                }
        }
        __syncthreads();
    }

    // ---- epilogue ----
    #pragma unroll
    for (int mi = 0; mi < 2; mi++) {
        #pragma unroll
        for (int nj = 0; nj < 4; nj++) {
            int row0 = m0 + wm + mi * 16 + lr;
            int coff = wn + nj * 8 + lc;
            if (mode == 0) {
                int h = blockIdx.x;
                uint16_t *dh, *dl;
                if (blockIdx.z == 0)      { dh = g_qh; dl = g_ql; }
                else if (blockIdx.z == 1) { dh = g_kh; dl = g_kl; }
                else                      { dh = g_vh; dl = g_vl; }
                #pragma unroll
                for (int rr = 0; rr < 2; rr++) {
                    int m = row0 + rr * 8;
                    int b = m >> 12, s = m & (S_ - 1);
                    size_t idx = (((size_t)b * H_ + h) * S_ + s) * HD_ + coff;
                    float a0 = acc[mi][nj][rr * 2], a1 = acc[mi][nj][rr * 2 + 1];
                    __nv_bfloat162 hb = __floats2bfloat162_rn(a0, a1);
                    __nv_bfloat162 lb = __floats2bfloat162_rn(a0 - __bfloat162float(hb.x),
                                                              a1 - __bfloat162float(hb.y));
                    *(uint32_t*)&dh[idx] = *(uint32_t*)&hb;
                    *(uint32_t*)&dl[idx] = *(uint32_t*)&lb;
                }
            } else {
                #pragma unroll
                for (int rr = 0; rr < 2; rr++) {
                    int m = row0 + rr * 8;
                    float* dst = &outp[(size_t)m * D_ + n0 + coff];
                    *(float2*)dst = make_float2(acc[mi][nj][rr * 2], acc[mi][nj][rr * 2 + 1]);
                }
            }
        }
    }
}

// ==========================================================================
// Kernel 2: HMMA BigBird attention (R11, epilogue now writes split ctx)
// ==========================================================================
#define AST_ 72
#define OFF_KH 0
#define OFF_KL (64 * AST_)
#define OFF_VH (2 * 64 * AST_)
#define OFF_VL (3 * 64 * AST_)
#define OFF_PEN_BYTES (4 * 64 * AST_ * 2)
#define PST_ 66
#define ATTN_SMEM (OFF_PEN_BYTES + 64 * PST_ * 4)

__global__ __launch_bounds__(128) void attn_mma_kernel(
    const float* __restrict__ to_mask,
    const float* __restrict__ band_mask,
    const float* __restrict__ from_mask,
    const float* __restrict__ fbm,
    const float* __restrict__ tbm,
    const int*   __restrict__ ga)
{
    uint16_t* sT = (uint16_t*)asmem;
    float* sPen = (float*)(asmem + OFF_PEN_BYTES);
    const uint32_t sb = cvta_s(asmem);

    const int x = blockIdx.x;
    const int l = (x == 0) ? 0 : (x == 1) ? (NB_ - 1) : (x - 1);
    const int h = blockIdx.y, b = blockIdx.z;
    const int tid = threadIdx.x;
    const int wid = tid >> 5, lane = tid & 31;
    const int lr = lane >> 2, lc = (lane & 3) << 1;
    const int g8 = lane >> 3, ln8 = lane & 7;
    const int wq0 = wid << 4;

    {
        const size_t qbase = (((size_t)b * H_ + h) * S_ + l * BS_) * HD_;
        #pragma unroll
        for (int i = 0; i < 4; i++) {
            int idx = i * 128 + tid;
            int r = idx >> 3, c8 = (idx & 7) << 3;
            *(uint4*)&sT[OFF_KH + r * AST_ + c8] = *(const uint4*)&g_qh[qbase + r * HD_ + c8];
            *(uint4*)&sT[OFF_KL + r * AST_ + c8] = *(const uint4*)&g_ql[qbase + r * HD_ + c8];
        }
    }
    __syncthreads();

    uint32_t qh[4][4], ql[4][4];
    {
        int arow = wq0 + ln8 + ((g8 & 1) ? 8 : 0);
        int acol8 = (g8 & 2) ? 8 : 0;
        #pragma unroll
        for (int ks = 0; ks < 4; ks++) {
            uint32_t ad = sb + (uint32_t)(OFF_KH + arow * AST_ + ks * 16 + acol8) * 2;
            LDSM4(qh[ks][0], qh[ks][1], qh[ks][2], qh[ks][3], ad);
            ad = sb + (uint32_t)(OFF_KL + arow * AST_ + ks * 16 + acol8) * 2;
            LDSM4(ql[ks][0], ql[ks][1], ql[ks][2], ql[ks][3], ad);
        }
    }

    int kb[8], mt[8], aux[8];
    int nk;
    const bool full = (l == 0 || l == NB_ - 1);
    if (full) {
        nk = NB_;
    } else {
        int gb = ((b * H_ + h) * NB_ + l) * MC_;
        int g0 = ga[gb], g1 = ga[gb + 1], g2 = ga[gb + 2];
        if (l == 1) {
            kb[0]=0; kb[1]=1; kb[2]=2; kb[3]=NB_-1; kb[4]=g0; kb[5]=g1; kb[6]=g2;
            mt[0]=0; mt[1]=0; mt[2]=0; mt[3]=0; mt[4]=2; mt[5]=2; mt[6]=2;
            aux[0]=0; aux[1]=0; aux[2]=0; aux[3]=0; aux[4]=g0; aux[5]=g1; aux[6]=g2;
            nk = 7;
        } else if (l == NB_ - 2) {
            kb[0]=0; kb[1]=NB_-3; kb[2]=NB_-2; kb[3]=NB_-1; kb[4]=g0; kb[5]=g1; kb[6]=g2;
            mt[0]=0; mt[1]=0; mt[2]=0; mt[3]=0; mt[4]=2; mt[5]=2; mt[6]=2;
            aux[0]=0; aux[1]=0; aux[2]=0; aux[3]=0; aux[4]=g0; aux[5]=g1; aux[6]=g2;
            nk = 7;
        } else {
            kb[0]=0; kb[1]=l-1; kb[2]=l; kb[3]=l+1; kb[4]=g0; kb[5]=g1; kb[6]=g2; kb[7]=NB_-1;
            mt[0]=0; mt[1]=1; mt[2]=1; mt[3]=1; mt[4]=2; mt[5]=2; mt[6]=2; mt[7]=0;
            aux[0]=0; aux[1]=0; aux[2]=1; aux[3]=2; aux[4]=g0; aux[5]=g1; aux[6]=g2; aux[7]=0;
            nk = 8;
        }
    }

    float m0 = -1e30f, m1 = -1e30f, l0 = 0.0f, l1 = 0.0f;
    float acc_o[8][4];
    #pragma unroll
    for (int nj = 0; nj < 8; nj++)
        #pragma unroll
        for (int c = 0; c < 4; c++) acc_o[nj][c] = 0.0f;

    const int pr_c = tid & 63;
    const int pr_h = tid >> 6;

    for (int it = 0; it < nk; ++it) {
        const int blk   = full ? it : kb[it];
        const int mtype = full ? 0  : mt[it];
        const int a     = full ? 0  : aux[it];

        __syncthreads();

        {
            const size_t kvb = (((size_t)b * H_ + h) * S_ + blk * BS_) * HD_;
            #pragma unroll
            for (int i = 0; i < 4; i++) {
                int idx = i * 128 + tid;
                int r = idx >> 3, c8 = (idx & 7) << 3;
                *(uint4*)&sT[OFF_KH + r * AST_ + c8] = *(const uint4*)&g_kh[kvb + r * HD_ + c8];
                *(uint4*)&sT[OFF_KL + r * AST_ + c8] = *(const uint4*)&g_kl[kvb + r * HD_ + c8];
                *(uint4*)&sT[OFF_VH + r * AST_ + c8] = *(const uint4*)&g_vh[kvb + r * HD_ + c8];
                *(uint4*)&sT[OFF_VL + r * AST_ + c8] = *(const uint4*)&g_vl[kvb + r * HD_ + c8];
            }
        }
        if (mtype == 0) {
            float cm = to_mask[b * S_ + blk * BS_ + pr_c];
            float pv = (1.0f - cm) * PEN_;
            #pragma unroll
            for (int i = 0; i < 32; i++)
                sPen[(2 * i + pr_h) * PST_ + pr_c] = pv;
        } else if (mtype == 1) {
            const float* bmr = &band_mask[((size_t)(b * (NB_ - 4) + (l - 2)) * BS_) * (3 * BS_) + a * BS_ + pr_c];
            #pragma unroll
            for (int i = 0; i < 32; i++) {
                int r = 2 * i + pr_h;
                sPen[r * PST_ + pr_c] = (1.0f - bmr[(size_t)r * (3 * BS_)]) * PEN_;
            }
        } else {
            float cm = tbm[(b * NB_ + a) * BS_ + pr_c];
            #pragma unroll
            for (int i = 0; i < 32; i++) {
                int r = 2 * i + pr_h;
                float rm = fbm[(b * NB_ + l) * BS_ + r];
                sPen[r * PST_ + pr_c] = (1.0f - rm * cm) * PEN_;
            }
        }
        __syncthreads();

        float s[8][4];
        #pragma unroll
        for (int nj = 0; nj < 8; nj++)
            #pragma unroll
            for (int c = 0; c < 4; c++) s[nj][c] = 0.0f;

        {
            int brow = ln8 + ((g8 & 2) ? 8 : 0);
            int bcol8 = (g8 & 1) ? 8 : 0;
            #pragma unroll
            for (int ks = 0; ks < 4; ks++) {
                #pragma unroll
                for (int njp = 0; njp < 4; njp++) {
                    uint32_t kh[4], kl[4];
                    uint32_t ad = sb + (uint32_t)(OFF_KH + (njp * 16 + brow) * AST_ + ks * 16 + bcol8) * 2;
                    LDSM4(kh[0], kh[1], kh[2], kh[3], ad);
                    ad = sb + (uint32_t)(OFF_KL + (njp * 16 + brow) * AST_ + ks * 16 + bcol8) * 2;
                    LDSM4(kl[0], kl[1], kl[2], kl[3], ad);
                    mma16816(s[2 * njp],     qh[ks], &kh[0]);
                    mma16816(s[2 * njp],     qh[ks], &kl[0]);
                    mma16816(s[2 * njp],     ql[ks], &kh[0]);
                    mma16816(s[2 * njp + 1], qh[ks], &kh[2]);
                    mma16816(s[2 * njp + 1], qh[ks], &kl[2]);
                    mma16816(s[2 * njp + 1], ql[ks], &kh[2]);
                }
            }
        }

        const int r0 = wq0 + lr, r1 = r0 + 8;
        #pragma unroll
        for (int nj = 0; nj < 8; nj++) {
            float2 p0 = *(const float2*)&sPen[r0 * PST_ + nj * 8 + lc];
            float2 p1 = *(const float2*)&sPen[r1 * PST_ + nj * 8 + lc];
            s[nj][0] = s[nj][0] * SCALE_ + p0.x;
            s[nj][1] = s[nj][1] * SCALE_ + p0.y;
            s[nj][2] = s[nj][2] * SCALE_ + p1.x;
            s[nj][3] = s[nj][3] * SCALE_ + p1.y;
        }

        float mx0 = -1e30f, mx1 = -1e30f;
        #pragma unroll
        for (int nj = 0; nj < 8; nj++) {
            mx0 = fmaxf(mx0, fmaxf(s[nj][0], s[nj][1]));
            mx1 = fmaxf(mx1, fmaxf(s[nj][2], s[nj][3]));
        }
        #pragma unroll
        for (int off = 1; off < 4; off <<= 1) {
            mx0 = fmaxf(mx0, __shfl_xor_sync(0xffffffffu, mx0, off));
            mx1 = fmaxf(mx1, __shfl_xor_sync(0xffffffffu, mx1, off));
        }
        float mn0 = fmaxf(m0, mx0), mn1 = fmaxf(m1, mx1);
        float al0 = __expf(m0 - mn0), al1 = __expf(m1 - mn1);
        float rs0 = 0.0f, rs1 = 0.0f;
        #pragma unroll
        for (int nj = 0; nj < 8; nj++) {
            s[nj][0] = __expf(s[nj][0] - mn0);
            s[nj][1] = __expf(s[nj][1] - mn0);
            s[nj][2] = __expf(s[nj][2] - mn1);
            s[nj][3] = __expf(s[nj][3] - mn1);
            rs0 += s[nj][0] + s[nj][1];
            rs1 += s[nj][2] + s[nj][3];
        }
        #pragma unroll
        for (int off = 1; off < 4; off <<= 1) {
            rs0 += __shfl_xor_sync(0xffffffffu, rs0, off);
            rs1 += __shfl_xor_sync(0xffffffffu, rs1, off);
        }
        l0 = l0 * al0 + rs0;  l1 = l1 * al1 + rs1;
        m0 = mn0;  m1 = mn1;
        #pragma unroll
        for (int nj = 0; nj < 8; nj++) {
            acc_o[nj][0] *= al0; acc_o[nj][1] *= al0;
            acc_o[nj][2] *= al1; acc_o[nj][3] *= al1;
        }

        {
            int vrow = ln8 + ((g8 & 1) ? 8 : 0);
            int vcol8 = (g8 & 2) ? 8 : 0;
            #pragma unroll
            for (int ks = 0; ks < 4; ks++) {
                const int t0 = 2 * ks, t1 = 2 * ks + 1;
                uint32_t aPh[4], aPl[4];
                float ph, pl;
                aPh[0] = packbf(s[t0][0], s[t0][1]);
                aPh[1] = packbf(s[t0][2], s[t0][3]);
                aPh[2] = packbf(s[t1][0], s[t1][1]);
                aPh[3] = packbf(s[t1][2], s[t1][3]);
                {
                    __nv_bfloat162 hb;
                    *(uint32_t*)&hb = aPh[0];
                    ph = s[t0][0] - __bfloat162float(hb.x); pl = s[t0][1] - __bfloat162float(hb.y);
                    aPl[0] = packbf(ph, pl);
                    *(uint32_t*)&hb = aPh[1];
                    ph = s[t0][2] - __bfloat162float(hb.x); pl = s[t0][3] - __bfloat162float(hb.y);
                    aPl[1] = packbf(ph, pl);
                    *(uint32_t*)&hb = aPh[2];
                    ph = s[t1][0] - __bfloat162float(hb.x); pl = s[t1][1] - __bfloat162float(hb.y);
                    aPl[2] = packbf(ph, pl);
                    *(uint32_t*)&hb = aPh[3];
                    ph = s[t1][2] - __bfloat162float(hb.x); pl = s[t1][3] - __bfloat162float(hb.y);
                    aPl[3] = packbf(ph, pl);
                }
                #pragma unroll
                for (int njp = 0; njp < 4; njp++) {
                    uint32_t vh[4], vl[4];
                    uint32_t ad = sb + (uint32_t)(OFF_VH + (ks * 16 + vrow) * AST_ + njp * 16 + vcol8) * 2;
                    LDSM4T(vh[0], vh[1], vh[2], vh[3], ad);
                    ad = sb + (uint32_t)(OFF_VL + (ks * 16 + vrow) * AST_ + njp * 16 + vcol8) * 2;
                    LDSM4T(vl[0], vl[1], vl[2], vl[3], ad);
                    mma16816(acc_o[2 * njp],     aPh, &vh[0]);
                    mma16816(acc_o[2 * njp],     aPh, &vl[0]);
                    mma16816(acc_o[2 * njp],     aPl, &vh[0]);
                    mma16816(acc_o[2 * njp + 1], aPh, &vh[2]);
                    mma16816(acc_o[2 * njp + 1], aPh, &vl[2]);
                    mma16816(acc_o[2 * njp + 1], aPl, &vh[2]);
                }
            }
        }
    }

    // ---- normalize, from_mask, write SPLIT ctx ----
    {
        const int r0 = wq0 + lr, r1 = r0 + 8;
        int srow0 = l * BS_ + r0, srow1 = l * BS_ + r1;
        float inv0 = from_mask[b * S_ + srow0] / l0;
        float inv1 = from_mask[b * S_ + srow1] / l1;
        size_t base0 = ((size_t)b * S_ + srow0) * D_ + h * HD_;
        size_t base1 = ((size_t)b * S_ + srow1) * D_ + h * HD_;
        #pragma unroll
        for (int nj = 0; nj < 8; nj++) {
            float o0 = acc_o[nj][0] * inv0, o1 = acc_o[nj][1] * inv0;
            __nv_bfloat162 hb = __floats2bfloat162_rn(o0, o1);
            __nv_bfloat162 lb = __floats2bfloat162_rn(o0 - __bfloat162float(hb.x),
                                                      o1 - __bfloat162float(hb.y));
            *(uint32_t*)&g_ch[base0 + nj * 8 + lc] = *(uint32_t*)&hb;
            *(uint32_t*)&g_cl[base0 + nj * 8 + lc] = *(uint32_t*)&lb;
            float o2 = acc_o[nj][2] * inv1, o3 = acc_o[nj][3] * inv1;
            hb = __floats2bfloat162_rn(o2, o3);
            lb = __floats2bfloat162_rn(o2 - __bfloat162float(hb.x),
                                       o3 - __bfloat162float(hb.y));
            *(uint32_t*)&g_ch[base1 + nj * 8 + lc] = *(uint32_t*)&hb;
            *(uint32_t*)&g_cl[base1 + nj * 8 + lc] = *(uint32_t*)&lb;
        }
    }
}

// ==========================================================================
// launch
// ==========================================================================
extern "C" void kernel_launch(void* const* d_in, const int* in_sizes, int n_in,
                              void* d_out, int out_size)
{
    const float* hs        = (const float*)d_in[0];
    const float* Wq        = (const float*)d_in[1];
    const float* Wk        = (const float*)d_in[2];
    const float* Wv        = (const float*)d_in[3];
    const float* Wo        = (const float*)d_in[4];
    const float* band_mask = (const float*)d_in[5];
    const float* from_mask = (const float*)d_in[6];
    const float* to_mask   = (const float*)d_in[7];
    const float* fbm       = (const float*)d_in[8];
    const float* tbm       = (const float*)d_in[9];
    const int*   ga        = (const int*)  d_in[10];
    float* out = (float*)d_out;

    cudaFuncSetAttribute(attn_mma_kernel, cudaFuncAttributeMaxDynamicSharedMemorySize, ATTN_SMEM);
    cudaFuncSetAttribute(gemm2_kernel, cudaFuncAttributeMaxDynamicSharedMemorySize, G2_SMEM);

    const int nsplit = (HS_N / 4 + W_N) ;             // total float4 elements
    split_inputs_kernel<<<(nsplit + 255) / 256, 256>>>(hs, Wq, Wk, Wv, Wo);
    gemm2_kernel<<<dim3(12, 64, 3), 256, G2_SMEM>>>(nullptr, 0);
    attn_mma_kernel<<<dim3(NB_, H_, B_), 128, ATTN_SMEM>>>(to_mask, band_mask, from_mask, fbm, tbm, ga);
    gemm2_kernel<<<dim3(12, 64, 1), 256, G2_SMEM>>>(out, 1);
}

// round 13
// speedup vs baseline: 3.1361x; 1.0542x over previous
#include <cuda_runtime.h>
#include <cuda_bf16.h>
#include <cstdint>

// ---------------- problem constants ----------------
#define B_   2
#define H_   12
#define S_   4096
#define D_   768
#define BS_  64
#define HD_  64
#define NB_  64
#define MC_  3
#define PEN_ (-10000.0f)
#define SCALE_ 0.125f   // 1/sqrt(64)

#define HS_N (B_*S_*D_)      // 6291456
#define W_N  (D_*D_)         // 589824

// ---------------- scratch (device globals: allocation-free) ----------------
__device__ uint16_t g_ah[HS_N], g_al[HS_N];          // hidden_states hi/lo
__device__ uint16_t g_wh[4*W_N], g_wl[4*W_N];        // Wq,Wk,Wv,Wo hi/lo
__device__ uint16_t g_ch[HS_N], g_cl[HS_N];          // ctx hi/lo (attn epilogue)
__device__ uint16_t g_qh[B_*H_*S_*HD_], g_ql[B_*H_*S_*HD_];
__device__ uint16_t g_kh[B_*H_*S_*HD_], g_kl[B_*H_*S_*HD_];
__device__ uint16_t g_vh[B_*H_*S_*HD_], g_vl[B_*H_*S_*HD_];

// ---------------- helpers ----------------
__device__ __forceinline__ void mma16816(float* d, const uint32_t* a, const uint32_t* b) {
    asm volatile(
        "mma.sync.aligned.m16n8k16.row.col.f32.bf16.bf16.f32 "
        "{%0,%1,%2,%3}, {%4,%5,%6,%7}, {%8,%9}, {%0,%1,%2,%3};"
        : "+f"(d[0]), "+f"(d[1]), "+f"(d[2]), "+f"(d[3])
        : "r"(a[0]), "r"(a[1]), "r"(a[2]), "r"(a[3]), "r"(b[0]), "r"(b[1]));
}
__device__ __forceinline__ uint32_t cvta_s(const void* p) {
    uint32_t a;
    asm("{ .reg .u64 t; cvta.to.shared.u64 t, %1; cvt.u32.u64 %0, t; }" : "=r"(a) : "l"(p));
    return a;
}
#define LDSM4(R0,R1,R2,R3,A) \
    asm volatile("ldmatrix.sync.aligned.m8n8.x4.shared.b16 {%0,%1,%2,%3}, [%4];" \
                 : "=r"(R0), "=r"(R1), "=r"(R2), "=r"(R3) : "r"(A))
#define LDSM4T(R0,R1,R2,R3,A) \
    asm volatile("ldmatrix.sync.aligned.m8n8.x4.trans.shared.b16 {%0,%1,%2,%3}, [%4];" \
                 : "=r"(R0), "=r"(R1), "=r"(R2), "=r"(R3) : "r"(A))
__device__ __forceinline__ uint32_t packbf(float a, float b) {
    __nv_bfloat162 h = __floats2bfloat162_rn(a, b);
    return *(uint32_t*)&h;
}
__device__ __forceinline__ void cpasync16(uint32_t sdst, const void* gsrc) {
    asm volatile("cp.async.cg.shared.global [%0], [%1], 16;" :: "r"(sdst), "l"(gsrc));
}
#define CP_COMMIT() asm volatile("cp.async.commit_group;")

extern __shared__ char asmem[];

// ==========================================================================
// Kernel 0: split fp32 sources -> bf16 hi/lo
// ==========================================================================
__global__ void split_inputs_kernel(
    const float* __restrict__ hs,
    const float* __restrict__ W0, const float* __restrict__ W1,
    const float* __restrict__ W2, const float* __restrict__ W3)
{
    const int nHS4 = HS_N / 4, nW4 = W_N / 4;
    int i = blockIdx.x * blockDim.x + threadIdx.x;
    if (i >= nHS4 + 4 * nW4) return;
    const float4* src;
    uint16_t *dh, *dl;
    int off;
    if (i < nHS4) {
        src = (const float4*)hs; off = i; dh = g_ah; dl = g_al;
    } else {
        int j = i - nHS4;
        int z = j / nW4; off = j - z * nW4;
        src = (const float4*)(z == 0 ? W0 : z == 1 ? W1 : z == 2 ? W2 : W3);
        dh = g_wh + (size_t)z * W_N; dl = g_wl + (size_t)z * W_N;
    }
    float4 x = src[off];
    __nv_bfloat162 h01 = __floats2bfloat162_rn(x.x, x.y);
    __nv_bfloat162 h23 = __floats2bfloat162_rn(x.z, x.w);
    __nv_bfloat162 l01 = __floats2bfloat162_rn(x.x - __bfloat162float(h01.x),
                                               x.y - __bfloat162float(h01.y));
    __nv_bfloat162 l23 = __floats2bfloat162_rn(x.z - __bfloat162float(h23.x),
                                               x.w - __bfloat162float(h23.y));
    uint2 hv, lv;
    hv.x = *(uint32_t*)&h01; hv.y = *(uint32_t*)&h23;
    lv.x = *(uint32_t*)&l01; lv.y = *(uint32_t*)&l23;
    ((uint2*)dh)[off] = hv;
    ((uint2*)dl)[off] = lv;
}

// ==========================================================================
// Kernel 1: HMMA bf16x3 GEMM, cp.async double-buffered, LDSM fragment loads.
// CTA tile 128x64, K-chunk 32, 256 threads, warp tile 32x32.
// ==========================================================================
#define STR_ 40
#define SA_ELT(buf,hl) (((buf)*2+(hl))*128*STR_)
#define SB_ELT(buf,hl) (4*128*STR_ + ((buf)*2+(hl))*64*STR_)
#define G2_SMEM ((4*128*STR_ + 4*64*STR_) * 2)

__global__ __launch_bounds__(256) void gemm2_kernel(float* __restrict__ outp, int mode)
{
    const uint32_t sb = cvta_s(asmem);
    const int tid = threadIdx.x;
    const int wid = tid >> 5, lane = tid & 31;
    const int n0 = blockIdx.x << 6;
    const int m0 = blockIdx.y << 7;

    const uint16_t *Ah, *Al, *Wh, *Wl;
    if (mode == 0) {
        Ah = g_ah; Al = g_al;
        Wh = g_wh + (size_t)blockIdx.z * W_N;
        Wl = g_wl + (size_t)blockIdx.z * W_N;
    } else {
        Ah = g_ch; Al = g_cl;
        Wh = g_wh + (size_t)3 * W_N;
        Wl = g_wl + (size_t)3 * W_N;
    }

    const int wm = (wid & 3) << 5;
    const int wn = (wid >> 2) << 5;
    const int ar = tid >> 1, ac = (tid & 1) << 4;
    const int br = tid >> 2, bc = (tid & 3) << 3;
    const int lr = lane >> 2;
    const int lc = (lane & 3) << 1;
    const int g8 = lane >> 3, ln8 = lane & 7;

    float acc[2][4][4];
    #pragma unroll
    for (int mi = 0; mi < 2; mi++)
        #pragma unroll
        for (int nj = 0; nj < 4; nj++)
            #pragma unroll
            for (int c = 0; c < 4; c++) acc[mi][nj][c] = 0.0f;

    auto load_stage = [&](int buf, int k0) {
        size_t ga = (size_t)(m0 + ar) * D_ + k0 + ac;
        uint32_t da0 = sb + (uint32_t)(SA_ELT(buf,0) + ar * STR_ + ac) * 2;
        uint32_t da1 = sb + (uint32_t)(SA_ELT(buf,1) + ar * STR_ + ac) * 2;
        cpasync16(da0,      Ah + ga);
        cpasync16(da0 + 16, Ah + ga + 8);
        cpasync16(da1,      Al + ga);
        cpasync16(da1 + 16, Al + ga + 8);
        size_t gb = (size_t)(n0 + br) * D_ + k0 + bc;
        uint32_t db0 = sb + (uint32_t)(SB_ELT(buf,0) + br * STR_ + bc) * 2;
        uint32_t db1 = sb + (uint32_t)(SB_ELT(buf,1) + br * STR_ + bc) * 2;
        cpasync16(db0, Wh + gb);
        cpasync16(db1, Wl + gb);
        CP_COMMIT();
    };

    load_stage(0, 0);

    // ldmatrix lane geometry (same pattern as the attention kernel)
    const int a_ro = ln8 + ((g8 & 1) ? 8 : 0);   // + wm + mi*16
    const int a_co = (g8 & 2) ? 8 : 0;           // + ks*16
    const int b_ro = ln8 + ((g8 & 2) ? 8 : 0);   // + wn + njp*16
    const int b_co = (g8 & 1) ? 8 : 0;           // + ks*16

    const int NKC = D_ / 32;          // 24
    for (int kc = 0; kc < NKC; ++kc) {
        const int buf = kc & 1;
        if (kc + 1 < NKC) {
            load_stage(buf ^ 1, (kc + 1) * 32);
            asm volatile("cp.async.wait_group 1;" ::: "memory");
        } else {
            asm volatile("cp.async.wait_group 0;" ::: "memory");
        }
        __syncthreads();

        #pragma unroll
        for (int ks = 0; ks < 2; ++ks) {
            const int kk = ks * 16;
            uint32_t ah[2][4], al[2][4], bh[2][4], bl[2][4];
            #pragma unroll
            for (int mi = 0; mi < 2; mi++) {
                uint32_t ad = sb + (uint32_t)(SA_ELT(buf,0) + (wm + mi * 16 + a_ro) * STR_ + kk + a_co) * 2;
                LDSM4(ah[mi][0], ah[mi][1], ah[mi][2], ah[mi][3], ad);
                ad = sb + (uint32_t)(SA_ELT(buf,1) + (wm + mi * 16 + a_ro) * STR_ + kk + a_co) * 2;
                LDSM4(al[mi][0], al[mi][1], al[mi][2], al[mi][3], ad);
            }
            #pragma unroll
            for (int njp = 0; njp < 2; njp++) {
                uint32_t ad = sb + (uint32_t)(SB_ELT(buf,0) + (wn + njp * 16 + b_ro) * STR_ + kk + b_co) * 2;
                LDSM4(bh[njp][0], bh[njp][1], bh[njp][2], bh[njp][3], ad);
                ad = sb + (uint32_t)(SB_ELT(buf,1) + (wn + njp * 16 + b_ro) * STR_ + kk + b_co) * 2;
                LDSM4(bl[njp][0], bl[njp][1], bl[njp][2], bl[njp][3], ad);
            }
            #pragma unroll
            for (int mi = 0; mi < 2; mi++)
                #pragma unroll
                for (int njp = 0; njp < 2; njp++) {
                    mma16816(acc[mi][2*njp],     ah[mi], &bh[njp][0]);
                    mma16816(acc[mi][2*njp],     ah[mi], &bl[njp][0]);
                    mma16816(acc[mi][2*njp],     al[mi], &bh[njp][0]);
                    mma16816(acc[mi][2*njp + 1], ah[mi], &bh[njp][2]);
                    mma16816(acc[mi][2*njp + 1], ah[mi], &bl[njp][2]);
                    mma16816(acc[mi][2*njp + 1], al[mi], &bh[njp][2]);
                }
        }
        __syncthreads();
    }

    // ---- epilogue ----
    #pragma unroll
    for (int mi = 0; mi < 2; mi++) {
        #pragma unroll
        for (int nj = 0; nj < 4; nj++) {
            int row0 = m0 + wm + mi * 16 + lr;
            int coff = wn + nj * 8 + lc;
            if (mode == 0) {
                int h = blockIdx.x;
                uint16_t *dh, *dl;
                if (blockIdx.z == 0)      { dh = g_qh; dl = g_ql; }
                else if (blockIdx.z == 1) { dh = g_kh; dl = g_kl; }
                else                      { dh = g_vh; dl = g_vl; }
                #pragma unroll
                for (int rr = 0; rr < 2; rr++) {
                    int m = row0 + rr * 8;
                    int b = m >> 12, s = m & (S_ - 1);
                    size_t idx = (((size_t)b * H_ + h) * S_ + s) * HD_ + coff;
                    float a0 = acc[mi][nj][rr * 2], a1 = acc[mi][nj][rr * 2 + 1];
                    __nv_bfloat162 hb = __floats2bfloat162_rn(a0, a1);
                    __nv_bfloat162 lb = __floats2bfloat162_rn(a0 - __bfloat162float(hb.x),
                                                              a1 - __bfloat162float(hb.y));
                    *(uint32_t*)&dh[idx] = *(uint32_t*)&hb;
                    *(uint32_t*)&dl[idx] = *(uint32_t*)&lb;
                }
            } else {
                #pragma unroll
                for (int rr = 0; rr < 2; rr++) {
                    int m = row0 + rr * 8;
                    float* dst = &outp[(size_t)m * D_ + n0 + coff];
                    *(float2*)dst = make_float2(acc[mi][nj][rr * 2], acc[mi][nj][rr * 2 + 1]);
                }
            }
        }
    }
}

// ==========================================================================
// Kernel 2: HMMA BigBird attention (R12 version)
// ==========================================================================
#define AST_ 72
#define OFF_KH 0
#define OFF_KL (64 * AST_)
#define OFF_VH (2 * 64 * AST_)
#define OFF_VL (3 * 64 * AST_)
#define OFF_PEN_BYTES (4 * 64 * AST_ * 2)
#define PST_ 66
#define ATTN_SMEM (OFF_PEN_BYTES + 64 * PST_ * 4)

__global__ __launch_bounds__(128) void attn_mma_kernel(
    const float* __restrict__ to_mask,
    const float* __restrict__ band_mask,
    const float* __restrict__ from_mask,
    const float* __restrict__ fbm,
    const float* __restrict__ tbm,
    const int*   __restrict__ ga)
{
    uint16_t* sT = (uint16_t*)asmem;
    float* sPen = (float*)(asmem + OFF_PEN_BYTES);
    const uint32_t sb = cvta_s(asmem);

    const int x = blockIdx.x;
    const int l = (x == 0) ? 0 : (x == 1) ? (NB_ - 1) : (x - 1);
    const int h = blockIdx.y, b = blockIdx.z;
    const int tid = threadIdx.x;
    const int wid = tid >> 5, lane = tid & 31;
    const int lr = lane >> 2, lc = (lane & 3) << 1;
    const int g8 = lane >> 3, ln8 = lane & 7;
    const int wq0 = wid << 4;

    {
        const size_t qbase = (((size_t)b * H_ + h) * S_ + l * BS_) * HD_;
        #pragma unroll
        for (int i = 0; i < 4; i++) {
            int idx = i * 128 + tid;
            int r = idx >> 3, c8 = (idx & 7) << 3;
            *(uint4*)&sT[OFF_KH + r * AST_ + c8] = *(const uint4*)&g_qh[qbase + r * HD_ + c8];
            *(uint4*)&sT[OFF_KL + r * AST_ + c8] = *(const uint4*)&g_ql[qbase + r * HD_ + c8];
        }
    }
    __syncthreads();

    uint32_t qh[4][4], ql[4][4];
    {
        int arow = wq0 + ln8 + ((g8 & 1) ? 8 : 0);
        int acol8 = (g8 & 2) ? 8 : 0;
        #pragma unroll
        for (int ks = 0; ks < 4; ks++) {
            uint32_t ad = sb + (uint32_t)(OFF_KH + arow * AST_ + ks * 16 + acol8) * 2;
            LDSM4(qh[ks][0], qh[ks][1], qh[ks][2], qh[ks][3], ad);
            ad = sb + (uint32_t)(OFF_KL + arow * AST_ + ks * 16 + acol8) * 2;
            LDSM4(ql[ks][0], ql[ks][1], ql[ks][2], ql[ks][3], ad);
        }
    }

    int kb[8], mt[8], aux[8];
    int nk;
    const bool full = (l == 0 || l == NB_ - 1);
    if (full) {
        nk = NB_;
    } else {
        int gb = ((b * H_ + h) * NB_ + l) * MC_;
        int g0 = ga[gb], g1 = ga[gb + 1], g2 = ga[gb + 2];
        if (l == 1) {
            kb[0]=0; kb[1]=1; kb[2]=2; kb[3]=NB_-1; kb[4]=g0; kb[5]=g1; kb[6]=g2;
            mt[0]=0; mt[1]=0; mt[2]=0; mt[3]=0; mt[4]=2; mt[5]=2; mt[6]=2;
            aux[0]=0; aux[1]=0; aux[2]=0; aux[3]=0; aux[4]=g0; aux[5]=g1; aux[6]=g2;
            nk = 7;
        } else if (l == NB_ - 2) {
            kb[0]=0; kb[1]=NB_-3; kb[2]=NB_-2; kb[3]=NB_-1; kb[4]=g0; kb[5]=g1; kb[6]=g2;
            mt[0]=0; mt[1]=0; mt[2]=0; mt[3]=0; mt[4]=2; mt[5]=2; mt[6]=2;
            aux[0]=0; aux[1]=0; aux[2]=0; aux[3]=0; aux[4]=g0; aux[5]=g1; aux[6]=g2;
            nk = 7;
        } else {
            kb[0]=0; kb[1]=l-1; kb[2]=l; kb[3]=l+1; kb[4]=g0; kb[5]=g1; kb[6]=g2; kb[7]=NB_-1;
            mt[0]=0; mt[1]=1; mt[2]=1; mt[3]=1; mt[4]=2; mt[5]=2; mt[6]=2; mt[7]=0;
            aux[0]=0; aux[1]=0; aux[2]=1; aux[3]=2; aux[4]=g0; aux[5]=g1; aux[6]=g2; aux[7]=0;
            nk = 8;
        }
    }

    float m0 = -1e30f, m1 = -1e30f, l0 = 0.0f, l1 = 0.0f;
    float acc_o[8][4];
    #pragma unroll
    for (int nj = 0; nj < 8; nj++)
        #pragma unroll
        for (int c = 0; c < 4; c++) acc_o[nj][c] = 0.0f;

    const int pr_c = tid & 63;
    const int pr_h = tid >> 6;

    for (int it = 0; it < nk; ++it) {
        const int blk   = full ? it : kb[it];
        const int mtype = full ? 0  : mt[it];
        const int a     = full ? 0  : aux[it];

        __syncthreads();

        {
            const size_t kvb = (((size_t)b * H_ + h) * S_ + blk * BS_) * HD_;
            #pragma unroll
            for (int i = 0; i < 4; i++) {
                int idx = i * 128 + tid;
                int r = idx >> 3, c8 = (idx & 7) << 3;
                *(uint4*)&sT[OFF_KH + r * AST_ + c8] = *(const uint4*)&g_kh[kvb + r * HD_ + c8];
                *(uint4*)&sT[OFF_KL + r * AST_ + c8] = *(const uint4*)&g_kl[kvb + r * HD_ + c8];
                *(uint4*)&sT[OFF_VH + r * AST_ + c8] = *(const uint4*)&g_vh[kvb + r * HD_ + c8];
                *(uint4*)&sT[OFF_VL + r * AST_ + c8] = *(const uint4*)&g_vl[kvb + r * HD_ + c8];
            }
        }
        if (mtype == 0) {
            float cm = to_mask[b * S_ + blk * BS_ + pr_c];
            float pv = (1.0f - cm) * PEN_;
            #pragma unroll
            for (int i = 0; i < 32; i++)
                sPen[(2 * i + pr_h) * PST_ + pr_c] = pv;
        } else if (mtype == 1) {
            const float* bmr = &band_mask[((size_t)(b * (NB_ - 4) + (l - 2)) * BS_) * (3 * BS_) + a * BS_ + pr_c];
            #pragma unroll
            for (int i = 0; i < 32; i++) {
                int r = 2 * i + pr_h;
                sPen[r * PST_ + pr_c] = (1.0f - bmr[(size_t)r * (3 * BS_)]) * PEN_;
            }
        } else {
            float cm = tbm[(b * NB_ + a) * BS_ + pr_c];
            #pragma unroll
            for (int i = 0; i < 32; i++) {
                int r = 2 * i + pr_h;
                float rm = fbm[(b * NB_ + l) * BS_ + r];
                sPen[r * PST_ + pr_c] = (1.0f - rm * cm) * PEN_;
            }
        }
        __syncthreads();

        float s[8][4];
        #pragma unroll
        for (int nj = 0; nj < 8; nj++)
            #pragma unroll
            for (int c = 0; c < 4; c++) s[nj][c] = 0.0f;

        {
            int brow = ln8 + ((g8 & 2) ? 8 : 0);
            int bcol8 = (g8 & 1) ? 8 : 0;
            #pragma unroll
            for (int ks = 0; ks < 4; ks++) {
                #pragma unroll
                for (int njp = 0; njp < 4; njp++) {
                    uint32_t kh[4], kl[4];
                    uint32_t ad = sb + (uint32_t)(OFF_KH + (njp * 16 + brow) * AST_ + ks * 16 + bcol8) * 2;
                    LDSM4(kh[0], kh[1], kh[2], kh[3], ad);
                    ad = sb + (uint32_t)(OFF_KL + (njp * 16 + brow) * AST_ + ks * 16 + bcol8) * 2;
                    LDSM4(kl[0], kl[1], kl[2], kl[3], ad);
                    mma16816(s[2 * njp],     qh[ks], &kh[0]);
                    mma16816(s[2 * njp],     qh[ks], &kl[0]);
                    mma16816(s[2 * njp],     ql[ks], &kh[0]);
                    mma16816(s[2 * njp + 1], qh[ks], &kh[2]);
                    mma16816(s[2 * njp + 1], qh[ks], &kl[2]);
                    mma16816(s[2 * njp + 1], ql[ks], &kh[2]);
                }
            }
        }

        const int r0 = wq0 + lr, r1 = r0 + 8;
        #pragma unroll
        for (int nj = 0; nj < 8; nj++) {
            float2 p0 = *(const float2*)&sPen[r0 * PST_ + nj * 8 + lc];
            float2 p1 = *(const float2*)&sPen[r1 * PST_ + nj * 8 + lc];
            s[nj][0] = s[nj][0] * SCALE_ + p0.x;
            s[nj][1] = s[nj][1] * SCALE_ + p0.y;
            s[nj][2] = s[nj][2] * SCALE_ + p1.x;
            s[nj][3] = s[nj][3] * SCALE_ + p1.y;
        }

        float mx0 = -1e30f, mx1 = -1e30f;
        #pragma unroll
        for (int nj = 0; nj < 8; nj++) {
            mx0 = fmaxf(mx0, fmaxf(s[nj][0], s[nj][1]));
            mx1 = fmaxf(mx1, fmaxf(s[nj][2], s[nj][3]));
        }
        #pragma unroll
        for (int off = 1; off < 4; off <<= 1) {
            mx0 = fmaxf(mx0, __shfl_xor_sync(0xffffffffu, mx0, off));
            mx1 = fmaxf(mx1, __shfl_xor_sync(0xffffffffu, mx1, off));
        }
        float mn0 = fmaxf(m0, mx0), mn1 = fmaxf(m1, mx1);
        float al0 = __expf(m0 - mn0), al1 = __expf(m1 - mn1);
        float rs0 = 0.0f, rs1 = 0.0f;
        #pragma unroll
        for (int nj = 0; nj < 8; nj++) {
            s[nj][0] = __expf(s[nj][0] - mn0);
            s[nj][1] = __expf(s[nj][1] - mn0);
            s[nj][2] = __expf(s[nj][2] - mn1);
            s[nj][3] = __expf(s[nj][3] - mn1);
            rs0 += s[nj][0] + s[nj][1];
            rs1 += s[nj][2] + s[nj][3];
        }
        #pragma unroll
        for (int off = 1; off < 4; off <<= 1) {
            rs0 += __shfl_xor_sync(0xffffffffu, rs0, off);
            rs1 += __shfl_xor_sync(0xffffffffu, rs1, off);
        }
        l0 = l0 * al0 + rs0;  l1 = l1 * al1 + rs1;
        m0 = mn0;  m1 = mn1;
        #pragma unroll
        for (int nj = 0; nj < 8; nj++) {
            acc_o[nj][0] *= al0; acc_o[nj][1] *= al0;
            acc_o[nj][2] *= al1; acc_o[nj][3] *= al1;
        }

        {
            int vrow = ln8 + ((g8 & 1) ? 8 : 0);
            int vcol8 = (g8 & 2) ? 8 : 0;
            #pragma unroll
            for (int ks = 0; ks < 4; ks++) {
                const int t0 = 2 * ks, t1 = 2 * ks + 1;
                uint32_t aPh[4], aPl[4];
                float ph, pl;
                aPh[0] = packbf(s[t0][0], s[t0][1]);
                aPh[1] = packbf(s[t0][2], s[t0][3]);
                aPh[2] = packbf(s[t1][0], s[t1][1]);
                aPh[3] = packbf(s[t1][2], s[t1][3]);
                {
                    __nv_bfloat162 hb;
                    *(uint32_t*)&hb = aPh[0];
                    ph = s[t0][0] - __bfloat162float(hb.x); pl = s[t0][1] - __bfloat162float(hb.y);
                    aPl[0] = packbf(ph, pl);
                    *(uint32_t*)&hb = aPh[1];
                    ph = s[t0][2] - __bfloat162float(hb.x); pl = s[t0][3] - __bfloat162float(hb.y);
                    aPl[1] = packbf(ph, pl);
                    *(uint32_t*)&hb = aPh[2];
                    ph = s[t1][0] - __bfloat162float(hb.x); pl = s[t1][1] - __bfloat162float(hb.y);
                    aPl[2] = packbf(ph, pl);
                    *(uint32_t*)&hb = aPh[3];
                    ph = s[t1][2] - __bfloat162float(hb.x); pl = s[t1][3] - __bfloat162float(hb.y);
                    aPl[3] = packbf(ph, pl);
                }
                #pragma unroll
                for (int njp = 0; njp < 4; njp++) {
                    uint32_t vh[4], vl[4];
                    uint32_t ad = sb + (uint32_t)(OFF_VH + (ks * 16 + vrow) * AST_ + njp * 16 + vcol8) * 2;
                    LDSM4T(vh[0], vh[1], vh[2], vh[3], ad);
                    ad = sb + (uint32_t)(OFF_VL + (ks * 16 + vrow) * AST_ + njp * 16 + vcol8) * 2;
                    LDSM4T(vl[0], vl[1], vl[2], vl[3], ad);
                    mma16816(acc_o[2 * njp],     aPh, &vh[0]);
                    mma16816(acc_o[2 * njp],     aPh, &vl[0]);
                    mma16816(acc_o[2 * njp],     aPl, &vh[0]);
                    mma16816(acc_o[2 * njp + 1], aPh, &vh[2]);
                    mma16816(acc_o[2 * njp + 1], aPh, &vl[2]);
                    mma16816(acc_o[2 * njp + 1], aPl, &vh[2]);
                }
            }
        }
    }

    {
        const int r0 = wq0 + lr, r1 = r0 + 8;
        int srow0 = l * BS_ + r0, srow1 = l * BS_ + r1;
        float inv0 = from_mask[b * S_ + srow0] / l0;
        float inv1 = from_mask[b * S_ + srow1] / l1;
        size_t base0 = ((size_t)b * S_ + srow0) * D_ + h * HD_;
        size_t base1 = ((size_t)b * S_ + srow1) * D_ + h * HD_;
        #pragma unroll
        for (int nj = 0; nj < 8; nj++) {
            float o0 = acc_o[nj][0] * inv0, o1 = acc_o[nj][1] * inv0;
            __nv_bfloat162 hb = __floats2bfloat162_rn(o0, o1);
            __nv_bfloat162 lb = __floats2bfloat162_rn(o0 - __bfloat162float(hb.x),
                                                      o1 - __bfloat162float(hb.y));
            *(uint32_t*)&g_ch[base0 + nj * 8 + lc] = *(uint32_t*)&hb;
            *(uint32_t*)&g_cl[base0 + nj * 8 + lc] = *(uint32_t*)&lb;
            float o2 = acc_o[nj][2] * inv1, o3 = acc_o[nj][3] * inv1;
            hb = __floats2bfloat162_rn(o2, o3);
            lb = __floats2bfloat162_rn(o2 - __bfloat162float(hb.x),
                                       o3 - __bfloat162float(hb.y));
            *(uint32_t*)&g_ch[base1 + nj * 8 + lc] = *(uint32_t*)&hb;
            *(uint32_t*)&g_cl[base1 + nj * 8 + lc] = *(uint32_t*)&lb;
        }
    }
}

// ==========================================================================
// launch
// ==========================================================================
extern "C" void kernel_launch(void* const* d_in, const int* in_sizes, int n_in,
                              void* d_out, int out_size)
{
    const float* hs        = (const float*)d_in[0];
    const float* Wq        = (const float*)d_in[1];
    const float* Wk        = (const float*)d_in[2];
    const float* Wv        = (const float*)d_in[3];
    const float* Wo        = (const float*)d_in[4];
    const float* band_mask = (const float*)d_in[5];
    const float* from_mask = (const float*)d_in[6];
    const float* to_mask   = (const float*)d_in[7];
    const float* fbm       = (const float*)d_in[8];
    const float* tbm       = (const float*)d_in[9];
    const int*   ga        = (const int*)  d_in[10];
    float* out = (float*)d_out;

    cudaFuncSetAttribute(attn_mma_kernel, cudaFuncAttributeMaxDynamicSharedMemorySize, ATTN_SMEM);
    cudaFuncSetAttribute(gemm2_kernel, cudaFuncAttributeMaxDynamicSharedMemorySize, G2_SMEM);

    const int nsplit = (HS_N / 4 + W_N);
    split_inputs_kernel<<<(nsplit + 255) / 256, 256>>>(hs, Wq, Wk, Wv, Wo);
    gemm2_kernel<<<dim3(12, 64, 3), 256, G2_SMEM>>>(nullptr, 0);
    attn_mma_kernel<<<dim3(NB_, H_, B_), 128, ATTN_SMEM>>>(to_mask, band_mask, from_mask, fbm, tbm, ga);
    gemm2_kernel<<<dim3(12, 64, 1), 256, G2_SMEM>>>(out, 1);
}

// round 15
// speedup vs baseline: 3.2052x; 1.0220x over previous
#include <cuda_runtime.h>
#include <cuda_bf16.h>
#include <cstdint>

// ---------------- problem constants ----------------
#define B_   2
#define H_   12
#define S_   4096
#define D_   768
#define BS_  64
#define HD_  64
#define NB_  64
#define MC_  3
#define PEN_ (-10000.0f)
#define SCALE_ 0.125f   // 1/sqrt(64)

#define HS_N (B_*S_*D_)      // 6291456
#define W_N  (D_*D_)         // 589824

// ---------------- scratch (device globals: allocation-free) ----------------
__device__ uint16_t g_ah[HS_N], g_al[HS_N];          // hidden_states hi/lo
__device__ uint16_t g_wh[4*W_N], g_wl[4*W_N];        // Wq,Wk,Wv,Wo hi/lo
__device__ uint16_t g_ch[HS_N], g_cl[HS_N];          // ctx hi/lo (attn epilogue)
__device__ uint16_t g_qh[B_*H_*S_*HD_], g_ql[B_*H_*S_*HD_];
__device__ uint16_t g_kh[B_*H_*S_*HD_], g_kl[B_*H_*S_*HD_];
__device__ uint16_t g_vh[B_*H_*S_*HD_], g_vl[B_*H_*S_*HD_];

// ---------------- helpers ----------------
__device__ __forceinline__ void mma16816(float* d, const uint32_t* a, const uint32_t* b) {
    asm volatile(
        "mma.sync.aligned.m16n8k16.row.col.f32.bf16.bf16.f32 "
        "{%0,%1,%2,%3}, {%4,%5,%6,%7}, {%8,%9}, {%0,%1,%2,%3};"
        : "+f"(d[0]), "+f"(d[1]), "+f"(d[2]), "+f"(d[3])
        : "r"(a[0]), "r"(a[1]), "r"(a[2]), "r"(a[3]), "r"(b[0]), "r"(b[1]));
}
__device__ __forceinline__ uint32_t cvta_s(const void* p) {
    uint32_t a;
    asm("{ .reg .u64 t; cvta.to.shared.u64 t, %1; cvt.u32.u64 %0, t; }" : "=r"(a) : "l"(p));
    return a;
}
#define LDSM4(R0,R1,R2,R3,A) \
    asm volatile("ldmatrix.sync.aligned.m8n8.x4.shared.b16 {%0,%1,%2,%3}, [%4];" \
                 : "=r"(R0), "=r"(R1), "=r"(R2), "=r"(R3) : "r"(A))
#define LDSM4T(R0,R1,R2,R3,A) \
    asm volatile("ldmatrix.sync.aligned.m8n8.x4.trans.shared.b16 {%0,%1,%2,%3}, [%4];" \
                 : "=r"(R0), "=r"(R1), "=r"(R2), "=r"(R3) : "r"(A))
__device__ __forceinline__ uint32_t packbf(float a, float b) {
    __nv_bfloat162 h = __floats2bfloat162_rn(a, b);
    return *(uint32_t*)&h;
}
__device__ __forceinline__ void cpasync16(uint32_t sdst, const void* gsrc) {
    asm volatile("cp.async.cg.shared.global [%0], [%1], 16;" :: "r"(sdst), "l"(gsrc));
}
#define CP_COMMIT() asm volatile("cp.async.commit_group;")

extern __shared__ char asmem[];

// ==========================================================================
// Kernel 0: split fp32 sources -> bf16 hi/lo
// ==========================================================================
__global__ void split_inputs_kernel(
    const float* __restrict__ hs,
    const float* __restrict__ W0, const float* __restrict__ W1,
    const float* __restrict__ W2, const float* __restrict__ W3)
{
    const int nHS4 = HS_N / 4, nW4 = W_N / 4;
    int i = blockIdx.x * blockDim.x + threadIdx.x;
    if (i >= nHS4 + 4 * nW4) return;
    const float4* src;
    uint16_t *dh, *dl;
    int off;
    if (i < nHS4) {
        src = (const float4*)hs; off = i; dh = g_ah; dl = g_al;
    } else {
        int j = i - nHS4;
        int z = j / nW4; off = j - z * nW4;
        src = (const float4*)(z == 0 ? W0 : z == 1 ? W1 : z == 2 ? W2 : W3);
        dh = g_wh + (size_t)z * W_N; dl = g_wl + (size_t)z * W_N;
    }
    float4 x = src[off];
    __nv_bfloat162 h01 = __floats2bfloat162_rn(x.x, x.y);
    __nv_bfloat162 h23 = __floats2bfloat162_rn(x.z, x.w);
    __nv_bfloat162 l01 = __floats2bfloat162_rn(x.x - __bfloat162float(h01.x),
                                               x.y - __bfloat162float(h01.y));
    __nv_bfloat162 l23 = __floats2bfloat162_rn(x.z - __bfloat162float(h23.x),
                                               x.w - __bfloat162float(h23.y));
    uint2 hv, lv;
    hv.x = *(uint32_t*)&h01; hv.y = *(uint32_t*)&h23;
    lv.x = *(uint32_t*)&l01; lv.y = *(uint32_t*)&l23;
    ((uint2*)dh)[off] = hv;
    ((uint2*)dl)[off] = lv;
}

// ==========================================================================
// Kernel 1: HMMA bf16x3 GEMM, 128x128 CTA tile, 32x64 warp tile,
// cp.async double-buffered, LDSM fragment loads. 256 threads, 2 CTAs/SM.
// ==========================================================================
#define STR_ 40
#define SA_ELT(buf,hl) (((buf)*2+(hl))*128*STR_)
#define SB_ELT(buf,hl) (4*128*STR_ + ((buf)*2+(hl))*128*STR_)
#define G2_SMEM (8*128*STR_*2)     // 81920 B

__global__ __launch_bounds__(256, 2) void gemm2_kernel(float* __restrict__ outp, int mode)
{
    const uint32_t sb = cvta_s(asmem);
    const int tid = threadIdx.x;
    const int wid = tid >> 5, lane = tid & 31;
    const int n0 = blockIdx.x << 7;      // 768/128 = 6 n-tiles
    const int m0 = blockIdx.y << 7;      // 64 m-tiles

    const uint16_t *Ah, *Al, *Wh, *Wl;
    if (mode == 0) {
        Ah = g_ah; Al = g_al;
        Wh = g_wh + (size_t)blockIdx.z * W_N;
        Wl = g_wl + (size_t)blockIdx.z * W_N;
    } else {
        Ah = g_ch; Al = g_cl;
        Wh = g_wh + (size_t)3 * W_N;
        Wl = g_wl + (size_t)3 * W_N;
    }

    const int wm = (wid & 3) << 5;       // 0,32,64,96
    const int wn = (wid >> 2) << 6;      // 0,64
    const int ar = tid >> 1, ac = (tid & 1) << 4;   // rows 0..127, col 0/16
    const int lr = lane >> 2;
    const int lc = (lane & 3) << 1;
    const int g8 = lane >> 3, ln8 = lane & 7;

    float acc[2][8][4];
    #pragma unroll
    for (int mi = 0; mi < 2; mi++)
        #pragma unroll
        for (int nj = 0; nj < 8; nj++)
            #pragma unroll
            for (int c = 0; c < 4; c++) acc[mi][nj][c] = 0.0f;

    auto load_stage = [&](int buf, int k0) {
        size_t ga = (size_t)(m0 + ar) * D_ + k0 + ac;
        uint32_t da0 = sb + (uint32_t)(SA_ELT(buf,0) + ar * STR_ + ac) * 2;
        uint32_t da1 = sb + (uint32_t)(SA_ELT(buf,1) + ar * STR_ + ac) * 2;
        cpasync16(da0,      Ah + ga);
        cpasync16(da0 + 16, Ah + ga + 8);
        cpasync16(da1,      Al + ga);
        cpasync16(da1 + 16, Al + ga + 8);
        size_t gb = (size_t)(n0 + ar) * D_ + k0 + ac;
        uint32_t db0 = sb + (uint32_t)(SB_ELT(buf,0) + ar * STR_ + ac) * 2;
        uint32_t db1 = sb + (uint32_t)(SB_ELT(buf,1) + ar * STR_ + ac) * 2;
        cpasync16(db0,      Wh + gb);
        cpasync16(db0 + 16, Wh + gb + 8);
        cpasync16(db1,      Wl + gb);
        cpasync16(db1 + 16, Wl + gb + 8);
        CP_COMMIT();
    };

    load_stage(0, 0);

    const int a_ro = ln8 + ((g8 & 1) ? 8 : 0);
    const int a_co = (g8 & 2) ? 8 : 0;
    const int b_ro = ln8 + ((g8 & 2) ? 8 : 0);
    const int b_co = (g8 & 1) ? 8 : 0;

    const int NKC = D_ / 32;          // 24
    for (int kc = 0; kc < NKC; ++kc) {
        const int buf = kc & 1;
        if (kc + 1 < NKC) {
            load_stage(buf ^ 1, (kc + 1) * 32);
            asm volatile("cp.async.wait_group 1;" ::: "memory");
        } else {
            asm volatile("cp.async.wait_group 0;" ::: "memory");
        }
        __syncthreads();

        #pragma unroll
        for (int ks = 0; ks < 2; ++ks) {
            const int kk = ks * 16;
            uint32_t ah[2][4], al[2][4], bh[4][4], bl[4][4];
            #pragma unroll
            for (int mi = 0; mi < 2; mi++) {
                uint32_t ad = sb + (uint32_t)(SA_ELT(buf,0) + (wm + mi * 16 + a_ro) * STR_ + kk + a_co) * 2;
                LDSM4(ah[mi][0], ah[mi][1], ah[mi][2], ah[mi][3], ad);
                ad = sb + (uint32_t)(SA_ELT(buf,1) + (wm + mi * 16 + a_ro) * STR_ + kk + a_co) * 2;
                LDSM4(al[mi][0], al[mi][1], al[mi][2], al[mi][3], ad);
            }
            #pragma unroll
            for (int njp = 0; njp < 4; njp++) {
                uint32_t ad = sb + (uint32_t)(SB_ELT(buf,0) + (wn + njp * 16 + b_ro) * STR_ + kk + b_co) * 2;
                LDSM4(bh[njp][0], bh[njp][1], bh[njp][2], bh[njp][3], ad);
                ad = sb + (uint32_t)(SB_ELT(buf,1) + (wn + njp * 16 + b_ro) * STR_ + kk + b_co) * 2;
                LDSM4(bl[njp][0], bl[njp][1], bl[njp][2], bl[njp][3], ad);
            }
            #pragma unroll
            for (int mi = 0; mi < 2; mi++)
                #pragma unroll
                for (int njp = 0; njp < 4; njp++) {
                    mma16816(acc[mi][2*njp],     ah[mi], &bh[njp][0]);
                    mma16816(acc[mi][2*njp],     ah[mi], &bl[njp][0]);
                    mma16816(acc[mi][2*njp],     al[mi], &bh[njp][0]);
                    mma16816(acc[mi][2*njp + 1], ah[mi], &bh[njp][2]);
                    mma16816(acc[mi][2*njp + 1], ah[mi], &bl[njp][2]);
                    mma16816(acc[mi][2*njp + 1], al[mi], &bh[njp][2]);
                }
        }
        __syncthreads();
    }

    // ---- epilogue ----
    #pragma unroll
    for (int mi = 0; mi < 2; mi++) {
        #pragma unroll
        for (int nj = 0; nj < 8; nj++) {
            int row0 = m0 + wm + mi * 16 + lr;
            int coff = wn + nj * 8 + lc;          // 0..127 within n-tile
            if (mode == 0) {
                int h = (blockIdx.x << 1) + (coff >> 6);
                int hd0 = coff & 63;
                uint16_t *dh, *dl;
                if (blockIdx.z == 0)      { dh = g_qh; dl = g_ql; }
                else if (blockIdx.z == 1) { dh = g_kh; dl = g_kl; }
                else                      { dh = g_vh; dl = g_vl; }
                #pragma unroll
                for (int rr = 0; rr < 2; rr++) {
                    int m = row0 + rr * 8;
                    int b = m >> 12, s = m & (S_ - 1);
                    size_t idx = (((size_t)b * H_ + h) * S_ + s) * HD_ + hd0;
                    float a0 = acc[mi][nj][rr * 2], a1 = acc[mi][nj][rr * 2 + 1];
                    __nv_bfloat162 hb = __floats2bfloat162_rn(a0, a1);
                    __nv_bfloat162 lb = __floats2bfloat162_rn(a0 - __bfloat162float(hb.x),
                                                              a1 - __bfloat162float(hb.y));
                    *(uint32_t*)&dh[idx] = *(uint32_t*)&hb;
                    *(uint32_t*)&dl[idx] = *(uint32_t*)&lb;
                }
            } else {
                #pragma unroll
                for (int rr = 0; rr < 2; rr++) {
                    int m = row0 + rr * 8;
                    float* dst = &outp[(size_t)m * D_ + n0 + coff];
                    *(float2*)dst = make_float2(acc[mi][nj][rr * 2], acc[mi][nj][rr * 2 + 1]);
                }
            }
        }
    }
}

// ==========================================================================
// Kernel 2: HMMA BigBird attention (R13 version, unchanged)
// ==========================================================================
#define AST_ 72
#define OFF_KH 0
#define OFF_KL (64 * AST_)
#define OFF_VH (2 * 64 * AST_)
#define OFF_VL (3 * 64 * AST_)
#define OFF_PEN_BYTES (4 * 64 * AST_ * 2)
#define PST_ 66
#define ATTN_SMEM (OFF_PEN_BYTES + 64 * PST_ * 4)

__global__ __launch_bounds__(128) void attn_mma_kernel(
    const float* __restrict__ to_mask,
    const float* __restrict__ band_mask,
    const float* __restrict__ from_mask,
    const float* __restrict__ fbm,
    const float* __restrict__ tbm,
    const int*   __restrict__ ga)
{
    uint16_t* sT = (uint16_t*)asmem;
    float* sPen = (float*)(asmem + OFF_PEN_BYTES);
    const uint32_t sb = cvta_s(asmem);

    const int x = blockIdx.x;
    const int l = (x == 0) ? 0 : (x == 1) ? (NB_ - 1) : (x - 1);
    const int h = blockIdx.y, b = blockIdx.z;
    const int tid = threadIdx.x;
    const int wid = tid >> 5, lane = tid & 31;
    const int lr = lane >> 2, lc = (lane & 3) << 1;
    const int g8 = lane >> 3, ln8 = lane & 7;
    const int wq0 = wid << 4;

    {
        const size_t qbase = (((size_t)b * H_ + h) * S_ + l * BS_) * HD_;
        #pragma unroll
        for (int i = 0; i < 4; i++) {
            int idx = i * 128 + tid;
            int r = idx >> 3, c8 = (idx & 7) << 3;
            *(uint4*)&sT[OFF_KH + r * AST_ + c8] = *(const uint4*)&g_qh[qbase + r * HD_ + c8];
            *(uint4*)&sT[OFF_KL + r * AST_ + c8] = *(const uint4*)&g_ql[qbase + r * HD_ + c8];
        }
    }
    __syncthreads();

    uint32_t qh[4][4], ql[4][4];
    {
        int arow = wq0 + ln8 + ((g8 & 1) ? 8 : 0);
        int acol8 = (g8 & 2) ? 8 : 0;
        #pragma unroll
        for (int ks = 0; ks < 4; ks++) {
            uint32_t ad = sb + (uint32_t)(OFF_KH + arow * AST_ + ks * 16 + acol8) * 2;
            LDSM4(qh[ks][0], qh[ks][1], qh[ks][2], qh[ks][3], ad);
            ad = sb + (uint32_t)(OFF_KL + arow * AST_ + ks * 16 + acol8) * 2;
            LDSM4(ql[ks][0], ql[ks][1], ql[ks][2], ql[ks][3], ad);
        }
    }

    int kb[8], mt[8], aux[8];
    int nk;
    const bool full = (l == 0 || l == NB_ - 1);
    if (full) {
        nk = NB_;
    } else {
        int gb = ((b * H_ + h) * NB_ + l) * MC_;
        int g0 = ga[gb], g1 = ga[gb + 1], g2 = ga[gb + 2];
        if (l == 1) {
            kb[0]=0; kb[1]=1; kb[2]=2; kb[3]=NB_-1; kb[4]=g0; kb[5]=g1; kb[6]=g2;
            mt[0]=0; mt[1]=0; mt[2]=0; mt[3]=0; mt[4]=2; mt[5]=2; mt[6]=2;
            aux[0]=0; aux[1]=0; aux[2]=0; aux[3]=0; aux[4]=g0; aux[5]=g1; aux[6]=g2;
            nk = 7;
        } else if (l == NB_ - 2) {
            kb[0]=0; kb[1]=NB_-3; kb[2]=NB_-2; kb[3]=NB_-1; kb[4]=g0; kb[5]=g1; kb[6]=g2;
            mt[0]=0; mt[1]=0; mt[2]=0; mt[3]=0; mt[4]=2; mt[5]=2; mt[6]=2;
            aux[0]=0; aux[1]=0; aux[2]=0; aux[3]=0; aux[4]=g0; aux[5]=g1; aux[6]=g2;
            nk = 7;
        } else {
            kb[0]=0; kb[1]=l-1; kb[2]=l; kb[3]=l+1; kb[4]=g0; kb[5]=g1; kb[6]=g2; kb[7]=NB_-1;
            mt[0]=0; mt[1]=1; mt[2]=1; mt[3]=1; mt[4]=2; mt[5]=2; mt[6]=2; mt[7]=0;
            aux[0]=0; aux[1]=0; aux[2]=1; aux[3]=2; aux[4]=g0; aux[5]=g1; aux[6]=g2; aux[7]=0;
            nk = 8;
        }
    }

    float m0 = -1e30f, m1 = -1e30f, l0 = 0.0f, l1 = 0.0f;
    float acc_o[8][4];
    #pragma unroll
    for (int nj = 0; nj < 8; nj++)
        #pragma unroll
        for (int c = 0; c < 4; c++) acc_o[nj][c] = 0.0f;

    const int pr_c = tid & 63;
    const int pr_h = tid >> 6;

    for (int it = 0; it < nk; ++it) {
        const int blk   = full ? it : kb[it];
        const int mtype = full ? 0  : mt[it];
        const int a     = full ? 0  : aux[it];

        __syncthreads();

        {
            const size_t kvb = (((size_t)b * H_ + h) * S_ + blk * BS_) * HD_;
            #pragma unroll
            for (int i = 0; i < 4; i++) {
                int idx = i * 128 + tid;
                int r = idx >> 3, c8 = (idx & 7) << 3;
                *(uint4*)&sT[OFF_KH + r * AST_ + c8] = *(const uint4*)&g_kh[kvb + r * HD_ + c8];
                *(uint4*)&sT[OFF_KL + r * AST_ + c8] = *(const uint4*)&g_kl[kvb + r * HD_ + c8];
                *(uint4*)&sT[OFF_VH + r * AST_ + c8] = *(const uint4*)&g_vh[kvb + r * HD_ + c8];
                *(uint4*)&sT[OFF_VL + r * AST_ + c8] = *(const uint4*)&g_vl[kvb + r * HD_ + c8];
            }
        }
        if (mtype == 0) {
            float cm = to_mask[b * S_ + blk * BS_ + pr_c];
            float pv = (1.0f - cm) * PEN_;
            #pragma unroll
            for (int i = 0; i < 32; i++)
                sPen[(2 * i + pr_h) * PST_ + pr_c] = pv;
        } else if (mtype == 1) {
            const float* bmr = &band_mask[((size_t)(b * (NB_ - 4) + (l - 2)) * BS_) * (3 * BS_) + a * BS_ + pr_c];
            #pragma unroll
            for (int i = 0; i < 32; i++) {
                int r = 2 * i + pr_h;
                sPen[r * PST_ + pr_c] = (1.0f - bmr[(size_t)r * (3 * BS_)]) * PEN_;
            }
        } else {
            float cm = tbm[(b * NB_ + a) * BS_ + pr_c];
            #pragma unroll
            for (int i = 0; i < 32; i++) {
                int r = 2 * i + pr_h;
                float rm = fbm[(b * NB_ + l) * BS_ + r];
                sPen[r * PST_ + pr_c] = (1.0f - rm * cm) * PEN_;
            }
        }
        __syncthreads();

        float s[8][4];
        #pragma unroll
        for (int nj = 0; nj < 8; nj++)
            #pragma unroll
            for (int c = 0; c < 4; c++) s[nj][c] = 0.0f;

        {
            int brow = ln8 + ((g8 & 2) ? 8 : 0);
            int bcol8 = (g8 & 1) ? 8 : 0;
            #pragma unroll
            for (int ks = 0; ks < 4; ks++) {
                #pragma unroll
                for (int njp = 0; njp < 4; njp++) {
                    uint32_t kh[4], kl[4];
                    uint32_t ad = sb + (uint32_t)(OFF_KH + (njp * 16 + brow) * AST_ + ks * 16 + bcol8) * 2;
                    LDSM4(kh[0], kh[1], kh[2], kh[3], ad);
                    ad = sb + (uint32_t)(OFF_KL + (njp * 16 + brow) * AST_ + ks * 16 + bcol8) * 2;
                    LDSM4(kl[0], kl[1], kl[2], kl[3], ad);
                    mma16816(s[2 * njp],     qh[ks], &kh[0]);
                    mma16816(s[2 * njp],     qh[ks], &kl[0]);
                    mma16816(s[2 * njp],     ql[ks], &kh[0]);
                    mma16816(s[2 * njp + 1], qh[ks], &kh[2]);
                    mma16816(s[2 * njp + 1], qh[ks], &kl[2]);
                    mma16816(s[2 * njp + 1], ql[ks], &kh[2]);
                }
            }
        }

        const int r0 = wq0 + lr, r1 = r0 + 8;
        #pragma unroll
        for (int nj = 0; nj < 8; nj++) {
            float2 p0 = *(const float2*)&sPen[r0 * PST_ + nj * 8 + lc];
            float2 p1 = *(const float2*)&sPen[r1 * PST_ + nj * 8 + lc];
            s[nj][0] = s[nj][0] * SCALE_ + p0.x;
            s[nj][1] = s[nj][1] * SCALE_ + p0.y;
            s[nj][2] = s[nj][2] * SCALE_ + p1.x;
            s[nj][3] = s[nj][3] * SCALE_ + p1.y;
        }

        float mx0 = -1e30f, mx1 = -1e30f;
        #pragma unroll
        for (int nj = 0; nj < 8; nj++) {
            mx0 = fmaxf(mx0, fmaxf(s[nj][0], s[nj][1]));
            mx1 = fmaxf(mx1, fmaxf(s[nj][2], s[nj][3]));
        }
        #pragma unroll
        for (int off = 1; off < 4; off <<= 1) {
            mx0 = fmaxf(mx0, __shfl_xor_sync(0xffffffffu, mx0, off));
            mx1 = fmaxf(mx1, __shfl_xor_sync(0xffffffffu, mx1, off));
        }
        float mn0 = fmaxf(m0, mx0), mn1 = fmaxf(m1, mx1);
        float al0 = __expf(m0 - mn0), al1 = __expf(m1 - mn1);
        float rs0 = 0.0f, rs1 = 0.0f;
        #pragma unroll
        for (int nj = 0; nj < 8; nj++) {
            s[nj][0] = __expf(s[nj][0] - mn0);
            s[nj][1] = __expf(s[nj][1] - mn0);
            s[nj][2] = __expf(s[nj][2] - mn1);
            s[nj][3] = __expf(s[nj][3] - mn1);
            rs0 += s[nj][0] + s[nj][1];
            rs1 += s[nj][2] + s[nj][3];
        }
        #pragma unroll
        for (int off = 1; off < 4; off <<= 1) {
            rs0 += __shfl_xor_sync(0xffffffffu, rs0, off);
            rs1 += __shfl_xor_sync(0xffffffffu, rs1, off);
        }
        l0 = l0 * al0 + rs0;  l1 = l1 * al1 + rs1;
        m0 = mn0;  m1 = mn1;
        #pragma unroll
        for (int nj = 0; nj < 8; nj++) {
            acc_o[nj][0] *= al0; acc_o[nj][1] *= al0;
            acc_o[nj][2] *= al1; acc_o[nj][3] *= al1;
        }

        {
            int vrow = ln8 + ((g8 & 1) ? 8 : 0);
            int vcol8 = (g8 & 2) ? 8 : 0;
            #pragma unroll
            for (int ks = 0; ks < 4; ks++) {
                const int t0 = 2 * ks, t1 = 2 * ks + 1;
                uint32_t aPh[4], aPl[4];
                float ph, pl;
                aPh[0] = packbf(s[t0][0], s[t0][1]);
                aPh[1] = packbf(s[t0][2], s[t0][3]);
                aPh[2] = packbf(s[t1][0], s[t1][1]);
                aPh[3] = packbf(s[t1][2], s[t1][3]);
                {
                    __nv_bfloat162 hb;
                    *(uint32_t*)&hb = aPh[0];
                    ph = s[t0][0] - __bfloat162float(hb.x); pl = s[t0][1] - __bfloat162float(hb.y);
                    aPl[0] = packbf(ph, pl);
                    *(uint32_t*)&hb = aPh[1];
                    ph = s[t0][2] - __bfloat162float(hb.x); pl = s[t0][3] - __bfloat162float(hb.y);
                    aPl[1] = packbf(ph, pl);
                    *(uint32_t*)&hb = aPh[2];
                    ph = s[t1][0] - __bfloat162float(hb.x); pl = s[t1][1] - __bfloat162float(hb.y);
                    aPl[2] = packbf(ph, pl);
                    *(uint32_t*)&hb = aPh[3];
                    ph = s[t1][2] - __bfloat162float(hb.x); pl = s[t1][3] - __bfloat162float(hb.y);
                    aPl[3] = packbf(ph, pl);
                }
                #pragma unroll
                for (int njp = 0; njp < 4; njp++) {
                    uint32_t vh[4], vl[4];
                    uint32_t ad = sb + (uint32_t)(OFF_VH + (ks * 16 + vrow) * AST_ + njp * 16 + vcol8) * 2;
                    LDSM4T(vh[0], vh[1], vh[2], vh[3], ad);
                    ad = sb + (uint32_t)(OFF_VL + (ks * 16 + vrow) * AST_ + njp * 16 + vcol8) * 2;
                    LDSM4T(vl[0], vl[1], vl[2], vl[3], ad);
                    mma16816(acc_o[2 * njp],     aPh, &vh[0]);
                    mma16816(acc_o[2 * njp],     aPh, &vl[0]);
                    mma16816(acc_o[2 * njp],     aPl, &vh[0]);
                    mma16816(acc_o[2 * njp + 1], aPh, &vh[2]);
                    mma16816(acc_o[2 * njp + 1], aPh, &vl[2]);
                    mma16816(acc_o[2 * njp + 1], aPl, &vh[2]);
                }
            }
        }
    }

    {
        const int r0 = wq0 + lr, r1 = r0 + 8;
        int srow0 = l * BS_ + r0, srow1 = l * BS_ + r1;
        float inv0 = from_mask[b * S_ + srow0] / l0;
        float inv1 = from_mask[b * S_ + srow1] / l1;
        size_t base0 = ((size_t)b * S_ + srow0) * D_ + h * HD_;
        size_t base1 = ((size_t)b * S_ + srow1) * D_ + h * HD_;
        #pragma unroll
        for (int nj = 0; nj < 8; nj++) {
            float o0 = acc_o[nj][0] * inv0, o1 = acc_o[nj][1] * inv0;
            __nv_bfloat162 hb = __floats2bfloat162_rn(o0, o1);
            __nv_bfloat162 lb = __floats2bfloat162_rn(o0 - __bfloat162float(hb.x),
                                                      o1 - __bfloat162float(hb.y));
            *(uint32_t*)&g_ch[base0 + nj * 8 + lc] = *(uint32_t*)&hb;
            *(uint32_t*)&g_cl[base0 + nj * 8 + lc] = *(uint32_t*)&lb;
            float o2 = acc_o[nj][2] * inv1, o3 = acc_o[nj][3] * inv1;
            hb = __floats2bfloat162_rn(o2, o3);
            lb = __floats2bfloat162_rn(o2 - __bfloat162float(hb.x),
                                       o3 - __bfloat162float(hb.y));
            *(uint32_t*)&g_ch[base1 + nj * 8 + lc] = *(uint32_t*)&hb;
            *(uint32_t*)&g_cl[base1 + nj * 8 + lc] = *(uint32_t*)&lb;
        }
    }
}

// ==========================================================================
// launch
// ==========================================================================
extern "C" void kernel_launch(void* const* d_in, const int* in_sizes, int n_in,
                              void* d_out, int out_size)
{
    const float* hs        = (const float*)d_in[0];
    const float* Wq        = (const float*)d_in[1];
    const float* Wk        = (const float*)d_in[2];
    const float* Wv        = (const float*)d_in[3];
    const float* Wo        = (const float*)d_in[4];
    const float* band_mask = (const float*)d_in[5];
    const float* from_mask = (const float*)d_in[6];
    const float* to_mask   = (const float*)d_in[7];
    const float* fbm       = (const float*)d_in[8];
    const float* tbm       = (const float*)d_in[9];
    const int*   ga        = (const int*)  d_in[10];
    float* out = (float*)d_out;

    cudaFuncSetAttribute(attn_mma_kernel, cudaFuncAttributeMaxDynamicSharedMemorySize, ATTN_SMEM);
    cudaFuncSetAttribute(gemm2_kernel, cudaFuncAttributeMaxDynamicSharedMemorySize, G2_SMEM);

    const int nsplit = (HS_N / 4 + W_N);
    split_inputs_kernel<<<(nsplit + 255) / 256, 256>>>(hs, Wq, Wk, Wv, Wo);
    gemm2_kernel<<<dim3(6, 64, 3), 256, G2_SMEM>>>(nullptr, 0);
    attn_mma_kernel<<<dim3(NB_, H_, B_), 128, ATTN_SMEM>>>(to_mask, band_mask, from_mask, fbm, tbm, ga);
    gemm2_kernel<<<dim3(6, 64, 1), 256, G2_SMEM>>>(out, 1);
}

// round 16
// speedup vs baseline: 3.8962x; 1.2156x over previous
#include <cuda_runtime.h>
#include <cuda_bf16.h>
#include <cstdint>

// ---------------- problem constants ----------------
#define B_   2
#define H_   12
#define S_   4096
#define D_   768
#define BS_  64
#define HD_  64
#define NB_  64
#define MC_  3
#define PEN_ (-10000.0f)
#define SCALE_ 0.125f   // 1/sqrt(64)

#define HS_N (B_*S_*D_)      // 6291456
#define W_N  (D_*D_)         // 589824

// ---------------- scratch (device globals: allocation-free) ----------------
__device__ uint16_t g_ah[HS_N], g_al[HS_N];
__device__ uint16_t g_wh[4*W_N], g_wl[4*W_N];
__device__ uint16_t g_ch[HS_N], g_cl[HS_N];
__device__ uint16_t g_qh[B_*H_*S_*HD_], g_ql[B_*H_*S_*HD_];
__device__ uint16_t g_kh[B_*H_*S_*HD_], g_kl[B_*H_*S_*HD_];
__device__ uint16_t g_vh[B_*H_*S_*HD_], g_vl[B_*H_*S_*HD_];
// split-KV partials for full rows (l=0, l=63): [row2][B][H][8 splits]
__device__ float g_pacc[2*B_*H_*8*64*64];   // 6.3 MB
__device__ float g_pm[2*B_*H_*8*64];
__device__ float g_pl[2*B_*H_*8*64];

// ---------------- helpers ----------------
__device__ __forceinline__ void mma16816(float* d, const uint32_t* a, const uint32_t* b) {
    asm volatile(
        "mma.sync.aligned.m16n8k16.row.col.f32.bf16.bf16.f32 "
        "{%0,%1,%2,%3}, {%4,%5,%6,%7}, {%8,%9}, {%0,%1,%2,%3};"
        : "+f"(d[0]), "+f"(d[1]), "+f"(d[2]), "+f"(d[3])
        : "r"(a[0]), "r"(a[1]), "r"(a[2]), "r"(a[3]), "r"(b[0]), "r"(b[1]));
}
__device__ __forceinline__ uint32_t cvta_s(const void* p) {
    uint32_t a;
    asm("{ .reg .u64 t; cvta.to.shared.u64 t, %1; cvt.u32.u64 %0, t; }" : "=r"(a) : "l"(p));
    return a;
}
#define LDSM4(R0,R1,R2,R3,A) \
    asm volatile("ldmatrix.sync.aligned.m8n8.x4.shared.b16 {%0,%1,%2,%3}, [%4];" \
                 : "=r"(R0), "=r"(R1), "=r"(R2), "=r"(R3) : "r"(A))
#define LDSM4T(R0,R1,R2,R3,A) \
    asm volatile("ldmatrix.sync.aligned.m8n8.x4.trans.shared.b16 {%0,%1,%2,%3}, [%4];" \
                 : "=r"(R0), "=r"(R1), "=r"(R2), "=r"(R3) : "r"(A))
__device__ __forceinline__ uint32_t packbf(float a, float b) {
    __nv_bfloat162 h = __floats2bfloat162_rn(a, b);
    return *(uint32_t*)&h;
}
__device__ __forceinline__ void cpasync16(uint32_t sdst, const void* gsrc) {
    asm volatile("cp.async.cg.shared.global [%0], [%1], 16;" :: "r"(sdst), "l"(gsrc));
}
#define CP_COMMIT() asm volatile("cp.async.commit_group;")

extern __shared__ char asmem[];

// ==========================================================================
// Kernel 0: split fp32 sources -> bf16 hi/lo
// ==========================================================================
__global__ void split_inputs_kernel(
    const float* __restrict__ hs,
    const float* __restrict__ W0, const float* __restrict__ W1,
    const float* __restrict__ W2, const float* __restrict__ W3)
{
    const int nHS4 = HS_N / 4, nW4 = W_N / 4;
    int i = blockIdx.x * blockDim.x + threadIdx.x;
    if (i >= nHS4 + 4 * nW4) return;
    const float4* src;
    uint16_t *dh, *dl;
    int off;
    if (i < nHS4) {
        src = (const float4*)hs; off = i; dh = g_ah; dl = g_al;
    } else {
        int j = i - nHS4;
        int z = j / nW4; off = j - z * nW4;
        src = (const float4*)(z == 0 ? W0 : z == 1 ? W1 : z == 2 ? W2 : W3);
        dh = g_wh + (size_t)z * W_N; dl = g_wl + (size_t)z * W_N;
    }
    float4 x = src[off];
    __nv_bfloat162 h01 = __floats2bfloat162_rn(x.x, x.y);
    __nv_bfloat162 h23 = __floats2bfloat162_rn(x.z, x.w);
    __nv_bfloat162 l01 = __floats2bfloat162_rn(x.x - __bfloat162float(h01.x),
                                               x.y - __bfloat162float(h01.y));
    __nv_bfloat162 l23 = __floats2bfloat162_rn(x.z - __bfloat162float(h23.x),
                                               x.w - __bfloat162float(h23.y));
    uint2 hv, lv;
    hv.x = *(uint32_t*)&h01; hv.y = *(uint32_t*)&h23;
    lv.x = *(uint32_t*)&l01; lv.y = *(uint32_t*)&l23;
    ((uint2*)dh)[off] = hv;
    ((uint2*)dl)[off] = lv;
}

// ==========================================================================
// Kernel 1: HMMA bf16x3 GEMM (R15: 128x128 CTA, 32x64 warp, cp.async DB)
// ==========================================================================
#define STR_ 40
#define SA_ELT(buf,hl) (((buf)*2+(hl))*128*STR_)
#define SB_ELT(buf,hl) (4*128*STR_ + ((buf)*2+(hl))*128*STR_)
#define G2_SMEM (8*128*STR_*2)

__global__ __launch_bounds__(256, 2) void gemm2_kernel(float* __restrict__ outp, int mode)
{
    const uint32_t sb = cvta_s(asmem);
    const int tid = threadIdx.x;
    const int wid = tid >> 5, lane = tid & 31;
    const int n0 = blockIdx.x << 7;
    const int m0 = blockIdx.y << 7;

    const uint16_t *Ah, *Al, *Wh, *Wl;
    if (mode == 0) {
        Ah = g_ah; Al = g_al;
        Wh = g_wh + (size_t)blockIdx.z * W_N;
        Wl = g_wl + (size_t)blockIdx.z * W_N;
    } else {
        Ah = g_ch; Al = g_cl;
        Wh = g_wh + (size_t)3 * W_N;
        Wl = g_wl + (size_t)3 * W_N;
    }

    const int wm = (wid & 3) << 5;
    const int wn = (wid >> 2) << 6;
    const int ar = tid >> 1, ac = (tid & 1) << 4;
    const int lr = lane >> 2;
    const int lc = (lane & 3) << 1;
    const int g8 = lane >> 3, ln8 = lane & 7;

    float acc[2][8][4];
    #pragma unroll
    for (int mi = 0; mi < 2; mi++)
        #pragma unroll
        for (int nj = 0; nj < 8; nj++)
            #pragma unroll
            for (int c = 0; c < 4; c++) acc[mi][nj][c] = 0.0f;

    auto load_stage = [&](int buf, int k0) {
        size_t ga = (size_t)(m0 + ar) * D_ + k0 + ac;
        uint32_t da0 = sb + (uint32_t)(SA_ELT(buf,0) + ar * STR_ + ac) * 2;
        uint32_t da1 = sb + (uint32_t)(SA_ELT(buf,1) + ar * STR_ + ac) * 2;
        cpasync16(da0,      Ah + ga);
        cpasync16(da0 + 16, Ah + ga + 8);
        cpasync16(da1,      Al + ga);
        cpasync16(da1 + 16, Al + ga + 8);
        size_t gb = (size_t)(n0 + ar) * D_ + k0 + ac;
        uint32_t db0 = sb + (uint32_t)(SB_ELT(buf,0) + ar * STR_ + ac) * 2;
        uint32_t db1 = sb + (uint32_t)(SB_ELT(buf,1) + ar * STR_ + ac) * 2;
        cpasync16(db0,      Wh + gb);
        cpasync16(db0 + 16, Wh + gb + 8);
        cpasync16(db1,      Wl + gb);
        cpasync16(db1 + 16, Wl + gb + 8);
        CP_COMMIT();
    };

    load_stage(0, 0);

    const int a_ro = ln8 + ((g8 & 1) ? 8 : 0);
    const int a_co = (g8 & 2) ? 8 : 0;
    const int b_ro = ln8 + ((g8 & 2) ? 8 : 0);
    const int b_co = (g8 & 1) ? 8 : 0;

    const int NKC = D_ / 32;
    for (int kc = 0; kc < NKC; ++kc) {
        const int buf = kc & 1;
        if (kc + 1 < NKC) {
            load_stage(buf ^ 1, (kc + 1) * 32);
            asm volatile("cp.async.wait_group 1;" ::: "memory");
        } else {
            asm volatile("cp.async.wait_group 0;" ::: "memory");
        }
        __syncthreads();

        #pragma unroll
        for (int ks = 0; ks < 2; ++ks) {
            const int kk = ks * 16;
            uint32_t ah[2][4], al[2][4], bh[4][4], bl[4][4];
            #pragma unroll
            for (int mi = 0; mi < 2; mi++) {
                uint32_t ad = sb + (uint32_t)(SA_ELT(buf,0) + (wm + mi * 16 + a_ro) * STR_ + kk + a_co) * 2;
                LDSM4(ah[mi][0], ah[mi][1], ah[mi][2], ah[mi][3], ad);
                ad = sb + (uint32_t)(SA_ELT(buf,1) + (wm + mi * 16 + a_ro) * STR_ + kk + a_co) * 2;
                LDSM4(al[mi][0], al[mi][1], al[mi][2], al[mi][3], ad);
            }
            #pragma unroll
            for (int njp = 0; njp < 4; njp++) {
                uint32_t ad = sb + (uint32_t)(SB_ELT(buf,0) + (wn + njp * 16 + b_ro) * STR_ + kk + b_co) * 2;
                LDSM4(bh[njp][0], bh[njp][1], bh[njp][2], bh[njp][3], ad);
                ad = sb + (uint32_t)(SB_ELT(buf,1) + (wn + njp * 16 + b_ro) * STR_ + kk + b_co) * 2;
                LDSM4(bl[njp][0], bl[njp][1], bl[njp][2], bl[njp][3], ad);
            }
            #pragma unroll
            for (int mi = 0; mi < 2; mi++)
                #pragma unroll
                for (int njp = 0; njp < 4; njp++) {
                    mma16816(acc[mi][2*njp],     ah[mi], &bh[njp][0]);
                    mma16816(acc[mi][2*njp],     ah[mi], &bl[njp][0]);
                    mma16816(acc[mi][2*njp],     al[mi], &bh[njp][0]);
                    mma16816(acc[mi][2*njp + 1], ah[mi], &bh[njp][2]);
                    mma16816(acc[mi][2*njp + 1], ah[mi], &bl[njp][2]);
                    mma16816(acc[mi][2*njp + 1], al[mi], &bh[njp][2]);
                }
        }
        __syncthreads();
    }

    #pragma unroll
    for (int mi = 0; mi < 2; mi++) {
        #pragma unroll
        for (int nj = 0; nj < 8; nj++) {
            int row0 = m0 + wm + mi * 16 + lr;
            int coff = wn + nj * 8 + lc;
            if (mode == 0) {
                int h = (blockIdx.x << 1) + (coff >> 6);
                int hd0 = coff & 63;
                uint16_t *dh, *dl;
                if (blockIdx.z == 0)      { dh = g_qh; dl = g_ql; }
                else if (blockIdx.z == 1) { dh = g_kh; dl = g_kl; }
                else                      { dh = g_vh; dl = g_vl; }
                #pragma unroll
                for (int rr = 0; rr < 2; rr++) {
                    int m = row0 + rr * 8;
                    int b = m >> 12, s = m & (S_ - 1);
                    size_t idx = (((size_t)b * H_ + h) * S_ + s) * HD_ + hd0;
                    float a0 = acc[mi][nj][rr * 2], a1 = acc[mi][nj][rr * 2 + 1];
                    __nv_bfloat162 hb = __floats2bfloat162_rn(a0, a1);
                    __nv_bfloat162 lb = __floats2bfloat162_rn(a0 - __bfloat162float(hb.x),
                                                              a1 - __bfloat162float(hb.y));
                    *(uint32_t*)&dh[idx] = *(uint32_t*)&hb;
                    *(uint32_t*)&dl[idx] = *(uint32_t*)&lb;
                }
            } else {
                #pragma unroll
                for (int rr = 0; rr < 2; rr++) {
                    int m = row0 + rr * 8;
                    float* dst = &outp[(size_t)m * D_ + n0 + coff];
                    *(float2*)dst = make_float2(acc[mi][nj][rr * 2], acc[mi][nj][rr * 2 + 1]);
                }
            }
        }
    }
}

// ==========================================================================
// Kernel 2: HMMA BigBird attention, split-KV for the two full rows.
// blockIdx.x in [0,78): x<62 -> normal row l=x+1; x>=62 -> full-row split:
// fi=x-62, row2=fi>>3 (0->l=0, 1->l=63), sp=fi&7, key blocks [8sp, 8sp+8).
// Split CTAs write unnormalized partials to g_pacc/g_pm/g_pl.
// ==========================================================================
#define AST_ 72
#define OFF_KH 0
#define OFF_KL (64 * AST_)
#define OFF_VH (2 * 64 * AST_)
#define OFF_VL (3 * 64 * AST_)
#define OFF_PEN_BYTES (4 * 64 * AST_ * 2)
#define PST_ 66
#define ATTN_SMEM (OFF_PEN_BYTES + 64 * PST_ * 4)

__global__ __launch_bounds__(128) void attn_mma_kernel(
    const float* __restrict__ to_mask,
    const float* __restrict__ band_mask,
    const float* __restrict__ from_mask,
    const float* __restrict__ fbm,
    const float* __restrict__ tbm,
    const int*   __restrict__ ga)
{
    uint16_t* sT = (uint16_t*)asmem;
    float* sPen = (float*)(asmem + OFF_PEN_BYTES);
    const uint32_t sb = cvta_s(asmem);

    const int x = blockIdx.x;
    const bool is_split = (x >= 62);
    int l, sp = 0, row2 = 0;
    if (!is_split) {
        l = x + 1;                       // rows 1..62
    } else {
        int fi = x - 62;
        row2 = fi >> 3; sp = fi & 7;
        l = row2 ? (NB_ - 1) : 0;
    }
    const int h = blockIdx.y, b = blockIdx.z;
    const int tid = threadIdx.x;
    const int wid = tid >> 5, lane = tid & 31;
    const int lr = lane >> 2, lc = (lane & 3) << 1;
    const int g8 = lane >> 3, ln8 = lane & 7;
    const int wq0 = wid << 4;

    {
        const size_t qbase = (((size_t)b * H_ + h) * S_ + l * BS_) * HD_;
        #pragma unroll
        for (int i = 0; i < 4; i++) {
            int idx = i * 128 + tid;
            int r = idx >> 3, c8 = (idx & 7) << 3;
            *(uint4*)&sT[OFF_KH + r * AST_ + c8] = *(const uint4*)&g_qh[qbase + r * HD_ + c8];
            *(uint4*)&sT[OFF_KL + r * AST_ + c8] = *(const uint4*)&g_ql[qbase + r * HD_ + c8];
        }
    }
    __syncthreads();

    uint32_t qh[4][4], ql[4][4];
    {
        int arow = wq0 + ln8 + ((g8 & 1) ? 8 : 0);
        int acol8 = (g8 & 2) ? 8 : 0;
        #pragma unroll
        for (int ks = 0; ks < 4; ks++) {
            uint32_t ad = sb + (uint32_t)(OFF_KH + arow * AST_ + ks * 16 + acol8) * 2;
            LDSM4(qh[ks][0], qh[ks][1], qh[ks][2], qh[ks][3], ad);
            ad = sb + (uint32_t)(OFF_KL + arow * AST_ + ks * 16 + acol8) * 2;
            LDSM4(ql[ks][0], ql[ks][1], ql[ks][2], ql[ks][3], ad);
        }
    }

    int kb[8], mt[8], aux[8];
    int nk;
    if (is_split) {
        nk = 8;
    } else {
        int gb = ((b * H_ + h) * NB_ + l) * MC_;
        int g0 = ga[gb], g1 = ga[gb + 1], g2 = ga[gb + 2];
        if (l == 1) {
            kb[0]=0; kb[1]=1; kb[2]=2; kb[3]=NB_-1; kb[4]=g0; kb[5]=g1; kb[6]=g2;
            mt[0]=0; mt[1]=0; mt[2]=0; mt[3]=0; mt[4]=2; mt[5]=2; mt[6]=2;
            aux[0]=0; aux[1]=0; aux[2]=0; aux[3]=0; aux[4]=g0; aux[5]=g1; aux[6]=g2;
            nk = 7;
        } else if (l == NB_ - 2) {
            kb[0]=0; kb[1]=NB_-3; kb[2]=NB_-2; kb[3]=NB_-1; kb[4]=g0; kb[5]=g1; kb[6]=g2;
            mt[0]=0; mt[1]=0; mt[2]=0; mt[3]=0; mt[4]=2; mt[5]=2; mt[6]=2;
            aux[0]=0; aux[1]=0; aux[2]=0; aux[3]=0; aux[4]=g0; aux[5]=g1; aux[6]=g2;
            nk = 7;
        } else {
            kb[0]=0; kb[1]=l-1; kb[2]=l; kb[3]=l+1; kb[4]=g0; kb[5]=g1; kb[6]=g2; kb[7]=NB_-1;
            mt[0]=0; mt[1]=1; mt[2]=1; mt[3]=1; mt[4]=2; mt[5]=2; mt[6]=2; mt[7]=0;
            aux[0]=0; aux[1]=0; aux[2]=1; aux[3]=2; aux[4]=g0; aux[5]=g1; aux[6]=g2; aux[7]=0;
            nk = 8;
        }
    }

    float m0 = -1e30f, m1 = -1e30f, l0 = 0.0f, l1 = 0.0f;
    float acc_o[8][4];
    #pragma unroll
    for (int nj = 0; nj < 8; nj++)
        #pragma unroll
        for (int c = 0; c < 4; c++) acc_o[nj][c] = 0.0f;

    const int pr_c = tid & 63;
    const int pr_h = tid >> 6;

    for (int it = 0; it < nk; ++it) {
        const int blk   = is_split ? (sp * 8 + it) : kb[it];
        const int mtype = is_split ? 0 : mt[it];
        const int a     = is_split ? 0 : aux[it];

        __syncthreads();

        {
            const size_t kvb = (((size_t)b * H_ + h) * S_ + blk * BS_) * HD_;
            #pragma unroll
            for (int i = 0; i < 4; i++) {
                int idx = i * 128 + tid;
                int r = idx >> 3, c8 = (idx & 7) << 3;
                *(uint4*)&sT[OFF_KH + r * AST_ + c8] = *(const uint4*)&g_kh[kvb + r * HD_ + c8];
                *(uint4*)&sT[OFF_KL + r * AST_ + c8] = *(const uint4*)&g_kl[kvb + r * HD_ + c8];
                *(uint4*)&sT[OFF_VH + r * AST_ + c8] = *(const uint4*)&g_vh[kvb + r * HD_ + c8];
                *(uint4*)&sT[OFF_VL + r * AST_ + c8] = *(const uint4*)&g_vl[kvb + r * HD_ + c8];
            }
        }
        if (mtype == 0) {
            float cm = to_mask[b * S_ + blk * BS_ + pr_c];
            float pv = (1.0f - cm) * PEN_;
            #pragma unroll
            for (int i = 0; i < 32; i++)
                sPen[(2 * i + pr_h) * PST_ + pr_c] = pv;
        } else if (mtype == 1) {
            const float* bmr = &band_mask[((size_t)(b * (NB_ - 4) + (l - 2)) * BS_) * (3 * BS_) + a * BS_ + pr_c];
            #pragma unroll
            for (int i = 0; i < 32; i++) {
                int r = 2 * i + pr_h;
                sPen[r * PST_ + pr_c] = (1.0f - bmr[(size_t)r * (3 * BS_)]) * PEN_;
            }
        } else {
            float cm = tbm[(b * NB_ + a) * BS_ + pr_c];
            #pragma unroll
            for (int i = 0; i < 32; i++) {
                int r = 2 * i + pr_h;
                float rm = fbm[(b * NB_ + l) * BS_ + r];
                sPen[r * PST_ + pr_c] = (1.0f - rm * cm) * PEN_;
            }
        }
        __syncthreads();

        float s[8][4];
        #pragma unroll
        for (int nj = 0; nj < 8; nj++)
            #pragma unroll
            for (int c = 0; c < 4; c++) s[nj][c] = 0.0f;

        {
            int brow = ln8 + ((g8 & 2) ? 8 : 0);
            int bcol8 = (g8 & 1) ? 8 : 0;
            #pragma unroll
            for (int ks = 0; ks < 4; ks++) {
                #pragma unroll
                for (int njp = 0; njp < 4; njp++) {
                    uint32_t kh[4], kl[4];
                    uint32_t ad = sb + (uint32_t)(OFF_KH + (njp * 16 + brow) * AST_ + ks * 16 + bcol8) * 2;
                    LDSM4(kh[0], kh[1], kh[2], kh[3], ad);
                    ad = sb + (uint32_t)(OFF_KL + (njp * 16 + brow) * AST_ + ks * 16 + bcol8) * 2;
                    LDSM4(kl[0], kl[1], kl[2], kl[3], ad);
                    mma16816(s[2 * njp],     qh[ks], &kh[0]);
                    mma16816(s[2 * njp],     qh[ks], &kl[0]);
                    mma16816(s[2 * njp],     ql[ks], &kh[0]);
                    mma16816(s[2 * njp + 1], qh[ks], &kh[2]);
                    mma16816(s[2 * njp + 1], qh[ks], &kl[2]);
                    mma16816(s[2 * njp + 1], ql[ks], &kh[2]);
                }
            }
        }

        const int r0 = wq0 + lr, r1 = r0 + 8;
        #pragma unroll
        for (int nj = 0; nj < 8; nj++) {
            float2 p0 = *(const float2*)&sPen[r0 * PST_ + nj * 8 + lc];
            float2 p1 = *(const float2*)&sPen[r1 * PST_ + nj * 8 + lc];
            s[nj][0] = s[nj][0] * SCALE_ + p0.x;
            s[nj][1] = s[nj][1] * SCALE_ + p0.y;
            s[nj][2] = s[nj][2] * SCALE_ + p1.x;
            s[nj][3] = s[nj][3] * SCALE_ + p1.y;
        }

        float mx0 = -1e30f, mx1 = -1e30f;
        #pragma unroll
        for (int nj = 0; nj < 8; nj++) {
            mx0 = fmaxf(mx0, fmaxf(s[nj][0], s[nj][1]));
            mx1 = fmaxf(mx1, fmaxf(s[nj][2], s[nj][3]));
        }
        #pragma unroll
        for (int off = 1; off < 4; off <<= 1) {
            mx0 = fmaxf(mx0, __shfl_xor_sync(0xffffffffu, mx0, off));
            mx1 = fmaxf(mx1, __shfl_xor_sync(0xffffffffu, mx1, off));
        }
        float mn0 = fmaxf(m0, mx0), mn1 = fmaxf(m1, mx1);
        float al0 = __expf(m0 - mn0), al1 = __expf(m1 - mn1);
        float rs0 = 0.0f, rs1 = 0.0f;
        #pragma unroll
        for (int nj = 0; nj < 8; nj++) {
            s[nj][0] = __expf(s[nj][0] - mn0);
            s[nj][1] = __expf(s[nj][1] - mn0);
            s[nj][2] = __expf(s[nj][2] - mn1);
            s[nj][3] = __expf(s[nj][3] - mn1);
            rs0 += s[nj][0] + s[nj][1];
            rs1 += s[nj][2] + s[nj][3];
        }
        #pragma unroll
        for (int off = 1; off < 4; off <<= 1) {
            rs0 += __shfl_xor_sync(0xffffffffu, rs0, off);
            rs1 += __shfl_xor_sync(0xffffffffu, rs1, off);
        }
        l0 = l0 * al0 + rs0;  l1 = l1 * al1 + rs1;
        m0 = mn0;  m1 = mn1;
        #pragma unroll
        for (int nj = 0; nj < 8; nj++) {
            acc_o[nj][0] *= al0; acc_o[nj][1] *= al0;
            acc_o[nj][2] *= al1; acc_o[nj][3] *= al1;
        }

        {
            int vrow = ln8 + ((g8 & 1) ? 8 : 0);
            int vcol8 = (g8 & 2) ? 8 : 0;
            #pragma unroll
            for (int ks = 0; ks < 4; ks++) {
                const int t0 = 2 * ks, t1 = 2 * ks + 1;
                uint32_t aPh[4], aPl[4];
                float ph, pl;
                aPh[0] = packbf(s[t0][0], s[t0][1]);
                aPh[1] = packbf(s[t0][2], s[t0][3]);
                aPh[2] = packbf(s[t1][0], s[t1][1]);
                aPh[3] = packbf(s[t1][2], s[t1][3]);
                {
                    __nv_bfloat162 hb;
                    *(uint32_t*)&hb = aPh[0];
                    ph = s[t0][0] - __bfloat162float(hb.x); pl = s[t0][1] - __bfloat162float(hb.y);
                    aPl[0] = packbf(ph, pl);
                    *(uint32_t*)&hb = aPh[1];
                    ph = s[t0][2] - __bfloat162float(hb.x); pl = s[t0][3] - __bfloat162float(hb.y);
                    aPl[1] = packbf(ph, pl);
                    *(uint32_t*)&hb = aPh[2];
                    ph = s[t1][0] - __bfloat162float(hb.x); pl = s[t1][1] - __bfloat162float(hb.y);
                    aPl[2] = packbf(ph, pl);
                    *(uint32_t*)&hb = aPh[3];
                    ph = s[t1][2] - __bfloat162float(hb.x); pl = s[t1][3] - __bfloat162float(hb.y);
                    aPl[3] = packbf(ph, pl);
                }
                #pragma unroll
                for (int njp = 0; njp < 4; njp++) {
                    uint32_t vh[4], vl[4];
                    uint32_t ad = sb + (uint32_t)(OFF_VH + (ks * 16 + vrow) * AST_ + njp * 16 + vcol8) * 2;
                    LDSM4T(vh[0], vh[1], vh[2], vh[3], ad);
                    ad = sb + (uint32_t)(OFF_VL + (ks * 16 + vrow) * AST_ + njp * 16 + vcol8) * 2;
                    LDSM4T(vl[0], vl[1], vl[2], vl[3], ad);
                    mma16816(acc_o[2 * njp],     aPh, &vh[0]);
                    mma16816(acc_o[2 * njp],     aPh, &vl[0]);
                    mma16816(acc_o[2 * njp],     aPl, &vh[0]);
                    mma16816(acc_o[2 * njp + 1], aPh, &vh[2]);
                    mma16816(acc_o[2 * njp + 1], aPh, &vl[2]);
                    mma16816(acc_o[2 * njp + 1], aPl, &vh[2]);
                }
            }
        }
    }

    const int r0 = wq0 + lr, r1 = r0 + 8;
    if (is_split) {
        // ---- write unnormalized partials ----
        const int pi = ((row2 * B_ + b) * H_ + h) * 8 + sp;
        float* pa = g_pacc + (size_t)pi * 4096;
        #pragma unroll
        for (int nj = 0; nj < 8; nj++) {
            *(float2*)&pa[r0 * 64 + nj * 8 + lc] = make_float2(acc_o[nj][0], acc_o[nj][1]);
            *(float2*)&pa[r1 * 64 + nj * 8 + lc] = make_float2(acc_o[nj][2], acc_o[nj][3]);
        }
        if ((lane & 3) == 0) {
            g_pm[pi * 64 + r0] = m0;  g_pl[pi * 64 + r0] = l0;
            g_pm[pi * 64 + r1] = m1;  g_pl[pi * 64 + r1] = l1;
        }
    } else {
        int srow0 = l * BS_ + r0, srow1 = l * BS_ + r1;
        float inv0 = from_mask[b * S_ + srow0] / l0;
        float inv1 = from_mask[b * S_ + srow1] / l1;
        size_t base0 = ((size_t)b * S_ + srow0) * D_ + h * HD_;
        size_t base1 = ((size_t)b * S_ + srow1) * D_ + h * HD_;
        #pragma unroll
        for (int nj = 0; nj < 8; nj++) {
            float o0 = acc_o[nj][0] * inv0, o1 = acc_o[nj][1] * inv0;
            __nv_bfloat162 hb = __floats2bfloat162_rn(o0, o1);
            __nv_bfloat162 lb = __floats2bfloat162_rn(o0 - __bfloat162float(hb.x),
                                                      o1 - __bfloat162float(hb.y));
            *(uint32_t*)&g_ch[base0 + nj * 8 + lc] = *(uint32_t*)&hb;
            *(uint32_t*)&g_cl[base0 + nj * 8 + lc] = *(uint32_t*)&lb;
            float o2 = acc_o[nj][2] * inv1, o3 = acc_o[nj][3] * inv1;
            hb = __floats2bfloat162_rn(o2, o3);
            lb = __floats2bfloat162_rn(o2 - __bfloat162float(hb.x),
                                       o3 - __bfloat162float(hb.y));
            *(uint32_t*)&g_ch[base1 + nj * 8 + lc] = *(uint32_t*)&hb;
            *(uint32_t*)&g_cl[base1 + nj * 8 + lc] = *(uint32_t*)&lb;
        }
    }
}

// ==========================================================================
// Kernel 3: merge split-KV partials for rows 0 and 63.
// grid (2, H, B), 256 threads. Per block: 64 q x 64 d outputs.
// ==========================================================================
__global__ __launch_bounds__(256) void attn_merge_kernel(const float* __restrict__ from_mask)
{
    __shared__ float sE[8][64];   // exp(m_s - M) per split, per q
    __shared__ float sL[64];      // merged denominator
    const int row2 = blockIdx.x, h = blockIdx.y, b = blockIdx.z;
    const int l = row2 ? (NB_ - 1) : 0;
    const int tid = threadIdx.x;
    const int pibase = ((row2 * B_ + b) * H_ + h) * 8;

    if (tid < 64) {
        float M = -1e30f;
        #pragma unroll
        for (int s = 0; s < 8; s++)
            M = fmaxf(M, g_pm[(pibase + s) * 64 + tid]);
        float L = 0.0f;
        #pragma unroll
        for (int s = 0; s < 8; s++) {
            float e = __expf(g_pm[(pibase + s) * 64 + tid] - M);
            sE[s][tid] = e;
            L += g_pl[(pibase + s) * 64 + tid] * e;
        }
        sL[tid] = L;
    }
    __syncthreads();

    // 4096 outputs, 16 per thread
    #pragma unroll
    for (int i = 0; i < 16; i++) {
        int e = tid + i * 256;
        int q = e >> 6, d = e & 63;
        float sum = 0.0f;
        #pragma unroll
        for (int s = 0; s < 8; s++)
            sum += g_pacc[(size_t)(pibase + s) * 4096 + q * 64 + d] * sE[s][q];
        int srow = l * BS_ + q;
        float o = sum / sL[q] * from_mask[b * S_ + srow];
        __nv_bfloat16 hb = __float2bfloat16(o);
        __nv_bfloat16 lb = __float2bfloat16(o - __bfloat162float(hb));
        size_t idx = ((size_t)b * S_ + srow) * D_ + h * HD_ + d;
        g_ch[idx] = *(uint16_t*)&hb;
        g_cl[idx] = *(uint16_t*)&lb;
    }
}

// ==========================================================================
// launch
// ==========================================================================
extern "C" void kernel_launch(void* const* d_in, const int* in_sizes, int n_in,
                              void* d_out, int out_size)
{
    const float* hs        = (const float*)d_in[0];
    const float* Wq        = (const float*)d_in[1];
    const float* Wk        = (const float*)d_in[2];
    const float* Wv        = (const float*)d_in[3];
    const float* Wo        = (const float*)d_in[4];
    const float* band_mask = (const float*)d_in[5];
    const float* from_mask = (const float*)d_in[6];
    const float* to_mask   = (const float*)d_in[7];
    const float* fbm       = (const float*)d_in[8];
    const float* tbm       = (const float*)d_in[9];
    const int*   ga        = (const int*)  d_in[10];
    float* out = (float*)d_out;

    cudaFuncSetAttribute(attn_mma_kernel, cudaFuncAttributeMaxDynamicSharedMemorySize, ATTN_SMEM);
    cudaFuncSetAttribute(gemm2_kernel, cudaFuncAttributeMaxDynamicSharedMemorySize, G2_SMEM);

    const int nsplit = (HS_N / 4 + W_N);
    split_inputs_kernel<<<(nsplit + 255) / 256, 256>>>(hs, Wq, Wk, Wv, Wo);
    gemm2_kernel<<<dim3(6, 64, 3), 256, G2_SMEM>>>(nullptr, 0);
    attn_mma_kernel<<<dim3(78, H_, B_), 128, ATTN_SMEM>>>(to_mask, band_mask, from_mask, fbm, tbm, ga);
    attn_merge_kernel<<<dim3(2, H_, B_), 256>>>(from_mask);
    gemm2_kernel<<<dim3(6, 64, 1), 256, G2_SMEM>>>(out, 1);
}